// round 1
// baseline (speedup 1.0000x reference)
#include <cuda_runtime.h>

// Problem constants
#define S    2048
#define HID  2560
#define NH   32
#define HD   80
#define RD   64
#define N_QKV (3*HID)          // 7680
#define SCALE 0.11180339887498949f   // 80^-0.5

// ---------------- scratch (device globals; no allocs allowed) ---------------
__device__ float g_q[NH * S * HD];
__device__ float g_k[NH * S * HD];
__device__ float g_v[NH * S * HD];
__device__ float g_attn[S * HID];

// ---------------- SGEMM: C[M,N] = A[M,K] * B[K,N] ---------------------------
// mode 0: plain row-major store to C
// mode 1: QKV scatter into g_q/g_k/g_v laid out [NH][S][HD]
#define BM 128
#define BN 128
#define BKK 16

__global__ __launch_bounds__(256)
void sgemm_kernel(const float* __restrict__ A, const float* __restrict__ B,
                  float* __restrict__ C, int M, int N, int K, int mode)
{
    __shared__ float As[BKK][BM];
    __shared__ float Bs[BKK][BN];

    const int tid = threadIdx.x;
    const int tx  = tid & 15;       // 0..15  (col group)
    const int ty  = tid >> 4;       // 0..15  (row group)
    const int rowBase = blockIdx.y * BM;
    const int colBase = blockIdx.x * BN;

    float acc[8][8];
#pragma unroll
    for (int i = 0; i < 8; i++)
#pragma unroll
        for (int j = 0; j < 8; j++) acc[i][j] = 0.f;

    const float* Aptr = A + (size_t)rowBase * K;

    for (int kt = 0; kt < K; kt += BKK) {
        // load A tile (128x16), store transposed As[k][m]
#pragma unroll
        for (int r = 0; r < 2; r++) {
            int i    = tid + r * 256;          // 0..511 float4 index
            int arow = i >> 2;                 // 0..127
            int acol = (i & 3) * 4;            // 0,4,8,12
            float4 v = *(const float4*)(Aptr + (size_t)arow * K + kt + acol);
            As[acol + 0][arow] = v.x;
            As[acol + 1][arow] = v.y;
            As[acol + 2][arow] = v.z;
            As[acol + 3][arow] = v.w;
        }
        // load B tile (16x128)
#pragma unroll
        for (int r = 0; r < 2; r++) {
            int i    = tid + r * 256;
            int brow = i >> 5;                 // 0..15
            int bcol = (i & 31) * 4;           // 0..124
            *(float4*)(&Bs[brow][bcol]) =
                *(const float4*)(B + (size_t)(kt + brow) * N + colBase + bcol);
        }
        __syncthreads();

#pragma unroll
        for (int k = 0; k < BKK; k++) {
            float a[8], b[8];
            *(float4*)(a)     = *(const float4*)(&As[k][ty * 8]);
            *(float4*)(a + 4) = *(const float4*)(&As[k][ty * 8 + 4]);
            *(float4*)(b)     = *(const float4*)(&Bs[k][tx * 8]);
            *(float4*)(b + 4) = *(const float4*)(&Bs[k][tx * 8 + 4]);
#pragma unroll
            for (int i = 0; i < 8; i++)
#pragma unroll
                for (int j = 0; j < 8; j++)
                    acc[i][j] = fmaf(a[i], b[j], acc[i][j]);
        }
        __syncthreads();
    }

    if (mode == 0) {
#pragma unroll
        for (int i = 0; i < 8; i++) {
            int row = rowBase + ty * 8 + i;
            float* crow = C + (size_t)row * N + colBase + tx * 8;
            *(float4*)(crow)     = *(float4*)(&acc[i][0]);
            *(float4*)(crow + 4) = *(float4*)(&acc[i][4]);
        }
    } else {
        // scatter into q/k/v buffers [NH][S][HD]
#pragma unroll
        for (int i = 0; i < 8; i++) {
            int row = rowBase + ty * 8 + i;        // sequence position
#pragma unroll
            for (int j = 0; j < 8; j++) {
                int col = colBase + tx * 8 + j;    // 0..7679
                int p   = col / HID;
                int rem = col - p * HID;
                int h   = rem / HD;
                int d   = rem - h * HD;
                float* dst = (p == 0) ? g_q : (p == 1) ? g_k : g_v;
                dst[((size_t)h * S + row) * HD + d] = acc[i][j];
            }
        }
    }
}

// ---------------- RoPE on q and k (first RD=64 dims of each head) -----------
__global__ void rope_kernel(const int* __restrict__ pos_ids)
{
    int idx = blockIdx.x * blockDim.x + threadIdx.x;   // NH*S*32 threads
    int d = idx & 31;
    int s = (idx >> 5) & (S - 1);
    int h = idx >> 16;
    if (h >= NH) return;

    float posf = (float)pos_ids[s];
    // inv_freq = 10000^(-d/32) = exp2(-d * log2(10000)/32)
    float inv  = exp2f(-0.415241011861f * (float)d);
    float ang  = posf * inv;
    float c, sn;
    sincosf(ang, &sn, &c);

    size_t base = ((size_t)h * S + s) * HD;
    float q1 = g_q[base + d], q2 = g_q[base + d + 32];
    g_q[base + d]      = q1 * c - q2 * sn;
    g_q[base + d + 32] = q2 * c + q1 * sn;
    float k1 = g_k[base + d], k2 = g_k[base + d + 32];
    g_k[base + d]      = k1 * c - k2 * sn;
    g_k[base + d + 32] = k2 * c + k1 * sn;
}

// ---------------- flash-style causal attention with ALiBi -------------------
#define QB 128
#define KB 64

__global__ __launch_bounds__(QB)
void attn_kernel(const int* __restrict__ pos_ids)
{
    const int h  = blockIdx.y;
    // reverse q-tile order: heaviest (largest causal span) blocks launch first
    const int qtile = gridDim.x - 1 - blockIdx.x;
    const int q0 = qtile * QB;
    const int q  = q0 + threadIdx.x;

    __shared__ float Ks[KB][HD];
    __shared__ float Vs[KB][HD];
    __shared__ float Kpos[KB];

    float qreg[HD];
    const float* qptr = g_q + ((size_t)h * S + q) * HD;
#pragma unroll
    for (int d = 0; d < HD; d++) qreg[d] = qptr[d] * SCALE;

    const float slope = exp2f(-0.25f * (float)(h + 1));
    const float posq  = (float)pos_ids[q];

    float m = -1e30f, l = 0.f;
    float acc[HD];
#pragma unroll
    for (int d = 0; d < HD; d++) acc[d] = 0.f;

    const int kend = q0 + QB;
    for (int kt = 0; kt < kend; kt += KB) {
        __syncthreads();
        const float* kp = g_k + ((size_t)h * S + kt) * HD;
        const float* vp = g_v + ((size_t)h * S + kt) * HD;
        for (int i = threadIdx.x; i < KB * HD; i += QB) {
            Ks[i / HD][i % HD] = kp[i];
            Vs[i / HD][i % HD] = vp[i];
        }
        if (threadIdx.x < KB) Kpos[threadIdx.x] = (float)pos_ids[kt + threadIdx.x];
        __syncthreads();

        int jmax = q - kt + 1;
        if (jmax > KB) jmax = KB;
        for (int j = 0; j < jmax; j++) {
            float sdot = 0.f;
#pragma unroll
            for (int d = 0; d < HD; d++) sdot = fmaf(qreg[d], Ks[j][d], sdot);
            float score = sdot + slope * (Kpos[j] - posq);
            if (score <= m) {
                float p = __expf(score - m);
                l += p;
#pragma unroll
                for (int d = 0; d < HD; d++) acc[d] = fmaf(p, Vs[j][d], acc[d]);
            } else {
                float corr = __expf(m - score);
                m = score;
                l = fmaf(l, corr, 1.f);
#pragma unroll
                for (int d = 0; d < HD; d++) acc[d] = fmaf(acc[d], corr, Vs[j][d]);
            }
        }
    }

    float invl = 1.f / l;
    float* op = g_attn + (size_t)q * HID + h * HD;
#pragma unroll
    for (int d = 0; d < HD; d++) op[d] = acc[d] * invl;
}

// ---------------- launch -----------------------------------------------------
extern "C" void kernel_launch(void* const* d_in, const int* in_sizes, int n_in,
                              void* d_out, int out_size)
{
    const int*   pos  = nullptr;
    const float* hs   = nullptr;
    const float* wqkv = nullptr;
    const float* wout = nullptr;
    for (int i = 0; i < n_in; i++) {
        switch (in_sizes[i]) {
            case S:                pos  = (const int*)d_in[i];   break;
            case S * HID:          hs   = (const float*)d_in[i]; break;
            case HID * N_QKV:      wqkv = (const float*)d_in[i]; break;
            case HID * HID:        wout = (const float*)d_in[i]; break;
        }
    }
    if (!pos || !hs || !wqkv || !wout) return;

    float* attn_ptr = nullptr;
    cudaGetSymbolAddress((void**)&attn_ptr, g_attn);

    // 1) QKV projection with scatter into per-head buffers
    {
        dim3 grid(N_QKV / BN, S / BM);
        sgemm_kernel<<<grid, 256>>>(hs, wqkv, nullptr, S, N_QKV, HID, 1);
    }
    // 2) RoPE
    {
        int total = NH * S * 32;
        rope_kernel<<<total / 256, 256>>>(pos);
    }
    // 3) attention
    {
        dim3 grid(S / QB, NH);
        attn_kernel<<<grid, QB>>>(pos);
    }
    // 4) output projection
    {
        dim3 grid(HID / BN, S / BM);
        sgemm_kernel<<<grid, 256>>>(attn_ptr, wout, (float*)d_out, S, HID, HID, 0);
    }
}

// round 3
// speedup vs baseline: 1.5240x; 1.5240x over previous
#include <cuda_runtime.h>
#include <cuda_bf16.h>
#include <cstdint>

// Problem constants
#define S    2048
#define HID  2560
#define NH   32
#define HD   80
#define N_QKV (3*HID)          // 7680
#define SCALE 0.11180339887498949f   // 80^-0.5

// ---------------- scratch (device globals; no allocs allowed) ---------------
__device__ float g_q[NH * S * HD];
__device__ float g_k[NH * S * HD];
__device__ float g_v[NH * S * HD];
__device__ float g_attn[S * HID];

__device__ __nv_bfloat16 g_a_hi[S * HID],      g_a_lo[S * HID];        // hidden (M,K)
__device__ __nv_bfloat16 g_wqkv_hi[N_QKV*HID], g_wqkv_lo[N_QKV*HID];   // (N,K) transposed
__device__ __nv_bfloat16 g_wout_hi[HID*HID],   g_wout_lo[HID*HID];     // (N,K) transposed
__device__ __nv_bfloat16 g_at_hi[S * HID],     g_at_lo[S * HID];       // attn out (M,K)

// ---------------- PTX helpers ------------------------------------------------
__device__ __forceinline__ uint32_t smem_u32(const void* p) {
    return (uint32_t)__cvta_generic_to_shared((void*)p);
}
__device__ __forceinline__ void cp16(uint32_t s, const void* g) {
    asm volatile("cp.async.cg.shared.global [%0], [%1], 16;" :: "r"(s), "l"(g) : "memory");
}
__device__ __forceinline__ void ldsm_x4(uint32_t* r, uint32_t addr) {
    asm volatile("ldmatrix.sync.aligned.m8n8.x4.shared.b16 {%0,%1,%2,%3}, [%4];"
                 : "=r"(r[0]), "=r"(r[1]), "=r"(r[2]), "=r"(r[3]) : "r"(addr));
}
__device__ __forceinline__ void ldsm_x2(uint32_t* r, uint32_t addr) {
    asm volatile("ldmatrix.sync.aligned.m8n8.x2.shared.b16 {%0,%1}, [%2];"
                 : "=r"(r[0]), "=r"(r[1]) : "r"(addr));
}
__device__ __forceinline__ void mma16816(float* d, const uint32_t* a, const uint32_t* b) {
    asm volatile("mma.sync.aligned.m16n8k16.row.col.f32.bf16.bf16.f32 "
                 "{%0,%1,%2,%3}, {%4,%5,%6,%7}, {%8,%9}, {%0,%1,%2,%3};"
                 : "+f"(d[0]), "+f"(d[1]), "+f"(d[2]), "+f"(d[3])
                 : "r"(a[0]), "r"(a[1]), "r"(a[2]), "r"(a[3]), "r"(b[0]), "r"(b[1]));
}

// ---------------- HMMA GEMM: D[M,N] = A[M,K] @ B[N,K]^T (bf16x3 split) ------
#define BMg 128
#define BNg 128
#define BKg 32
#define RSg 40                      // bf16 row stride (32 data + 8 pad)
#define TENg (128*RSg)              // bf16 elems per tensor tile (5120)
#define STAGEg (4*TENg)             // per stage (A_hi, A_lo, B_hi, B_lo)
#define GEMM_SMEM (2*STAGEg*2)      // bytes (81920)

__global__ __launch_bounds__(256)
void mma_gemm(const __nv_bfloat16* __restrict__ Ahi, const __nv_bfloat16* __restrict__ Alo,
              const __nv_bfloat16* __restrict__ Bhi, const __nv_bfloat16* __restrict__ Blo,
              float* __restrict__ C, int K, int N, int mode)
{
    extern __shared__ __align__(128) __nv_bfloat16 sm[];
    const int tid  = threadIdx.x;
    const int wid  = tid >> 5;
    const int lane = tid & 31;
    const int wr   = wid >> 2;      // 0..1  (64-row band)
    const int wc   = wid & 3;       // 0..3  (32-col band)
    const int rowBase = blockIdx.y * BMg;
    const int colBase = blockIdx.x * BNg;
    const uint32_t smbase = smem_u32(sm);

    float acc[4][4][4];
#pragma unroll
    for (int i = 0; i < 4; i++)
#pragma unroll
        for (int j = 0; j < 4; j++)
#pragma unroll
            for (int k = 0; k < 4; k++) acc[i][j][k] = 0.f;

    const int NC = K >> 5;

    // prologue: stage 0
    {
        const int kt = 0;
#pragma unroll
        for (int t = 0; t < 2; t++) {
            int idx = tid + t * 256;          // 0..511
            int row = idx >> 2, seg = idx & 3;
            uint32_t so = smbase + (uint32_t)(row * RSg + seg * 8) * 2;
            size_t gA = (size_t)(rowBase + row) * K + kt + seg * 8;
            size_t gB = (size_t)(colBase + row) * K + kt + seg * 8;
            cp16(so,                Ahi + gA);
            cp16(so + TENg * 2,     Alo + gA);
            cp16(so + 2 * TENg * 2, Bhi + gB);
            cp16(so + 3 * TENg * 2, Blo + gB);
        }
        asm volatile("cp.async.commit_group;" ::: "memory");
    }

    for (int c = 0; c < NC; c++) {
        const int s = c & 1;
        if (c + 1 < NC) {
            const int kt = (c + 1) << 5;
            const uint32_t sb = smbase + ((c + 1) & 1) * STAGEg * 2;
#pragma unroll
            for (int t = 0; t < 2; t++) {
                int idx = tid + t * 256;
                int row = idx >> 2, seg = idx & 3;
                uint32_t so = sb + (uint32_t)(row * RSg + seg * 8) * 2;
                size_t gA = (size_t)(rowBase + row) * K + kt + seg * 8;
                size_t gB = (size_t)(colBase + row) * K + kt + seg * 8;
                cp16(so,                Ahi + gA);
                cp16(so + TENg * 2,     Alo + gA);
                cp16(so + 2 * TENg * 2, Bhi + gB);
                cp16(so + 3 * TENg * 2, Blo + gB);
            }
        }
        asm volatile("cp.async.commit_group;" ::: "memory");
        asm volatile("cp.async.wait_group 1;" ::: "memory");
        __syncthreads();

        const uint32_t sb = smbase + s * STAGEg * 2;
#pragma unroll
        for (int ks = 0; ks < 2; ks++) {
            const int kof = ks * 16;
            uint32_t ah[4][4], al[4][4];
#pragma unroll
            for (int mf = 0; mf < 4; mf++) {
                int row = wr * 64 + mf * 16 + (lane & 15);
                int col = kof + (lane >> 4) * 8;
                uint32_t ad = sb + (uint32_t)(row * RSg + col) * 2;
                ldsm_x4(ah[mf], ad);
                ldsm_x4(al[mf], ad + TENg * 2);
            }
            uint32_t bh[4][2], bl[4][2];
#pragma unroll
            for (int nf = 0; nf < 4; nf++) {
                int brow = wc * 32 + nf * 8 + (lane & 7);
                int bcol = kof + ((lane >> 3) & 1) * 8;
                uint32_t bd = sb + 2 * TENg * 2 + (uint32_t)(brow * RSg + bcol) * 2;
                ldsm_x2(bh[nf], bd);
                ldsm_x2(bl[nf], bd + TENg * 2);
            }
#pragma unroll
            for (int mf = 0; mf < 4; mf++)
#pragma unroll
                for (int nf = 0; nf < 4; nf++) {
                    mma16816(acc[mf][nf], ah[mf], bh[nf]);
                    mma16816(acc[mf][nf], ah[mf], bl[nf]);
                    mma16816(acc[mf][nf], al[mf], bh[nf]);
                }
        }
        __syncthreads();
    }

    // epilogue
#pragma unroll
    for (int mf = 0; mf < 4; mf++) {
#pragma unroll
        for (int nf = 0; nf < 4; nf++) {
            int row = rowBase + wr * 64 + mf * 16 + (lane >> 2);
            int col = colBase + wc * 32 + nf * 8 + (lane & 3) * 2;
            if (mode == 0) {
                *(float2*)(C + (size_t)row * N + col) =
                    make_float2(acc[mf][nf][0], acc[mf][nf][1]);
                *(float2*)(C + (size_t)(row + 8) * N + col) =
                    make_float2(acc[mf][nf][2], acc[mf][nf][3]);
            } else {
                int p   = col / HID;
                int rem = col - p * HID;
                int h   = rem / HD;
                int d   = rem - h * HD;     // pair never crosses head (col even, HD even)
                float* dst = (p == 0) ? g_q : ((p == 1) ? g_k : g_v);
                *(float2*)(&dst[((size_t)h * S + row) * HD + d]) =
                    make_float2(acc[mf][nf][0], acc[mf][nf][1]);
                *(float2*)(&dst[((size_t)h * S + row + 8) * HD + d]) =
                    make_float2(acc[mf][nf][2], acc[mf][nf][3]);
            }
        }
    }
}

// ---------------- conversions ------------------------------------------------
__global__ void conv_split(const float* __restrict__ x, __nv_bfloat16* __restrict__ hi,
                           __nv_bfloat16* __restrict__ lo, int n)
{
    int i = blockIdx.x * blockDim.x + threadIdx.x;
    if (i >= n) return;
    float v = x[i];
    __nv_bfloat16 h = __float2bfloat16(v);
    hi[i] = h;
    lo[i] = __float2bfloat16(v - __bfloat162float(h));
}

// W[K,N] -> out[N,K] (hi/lo), tiled transpose
__global__ void convt_split(const float* __restrict__ W, __nv_bfloat16* __restrict__ hi,
                            __nv_bfloat16* __restrict__ lo, int K, int N)
{
    __shared__ float t[32][33];
    int n0 = blockIdx.x * 32, k0 = blockIdx.y * 32;
    for (int r = threadIdx.y; r < 32; r += 8)
        t[r][threadIdx.x] = W[(size_t)(k0 + r) * N + n0 + threadIdx.x];
    __syncthreads();
    for (int r = threadIdx.y; r < 32; r += 8) {
        float v = t[threadIdx.x][r];
        __nv_bfloat16 h = __float2bfloat16(v);
        size_t o = (size_t)(n0 + r) * K + k0 + threadIdx.x;
        hi[o] = h;
        lo[o] = __float2bfloat16(v - __bfloat162float(h));
    }
}

// ---------------- RoPE --------------------------------------------------------
__global__ void rope_kernel(const int* __restrict__ pos_ids)
{
    int idx = blockIdx.x * blockDim.x + threadIdx.x;   // NH*S*32 threads
    int d = idx & 31;
    int s = (idx >> 5) & (S - 1);
    int h = idx >> 16;
    if (h >= NH) return;

    float posf = (float)pos_ids[s];
    float inv  = exp2f(-0.415241011861f * (float)d);
    float ang  = posf * inv;
    float c, sn;
    sincosf(ang, &sn, &c);

    size_t base = ((size_t)h * S + s) * HD;
    float q1 = g_q[base + d], q2 = g_q[base + d + 32];
    g_q[base + d]      = q1 * c - q2 * sn;
    g_q[base + d + 32] = q2 * c + q1 * sn;
    float k1 = g_k[base + d], k2 = g_k[base + d + 32];
    g_k[base + d]      = k1 * c - k2 * sn;
    g_k[base + d + 32] = k2 * c + k1 * sn;
}

// ---------------- flash-style causal attention with ALiBi ---------------------
#define QB 128
#define KB 64

__global__ __launch_bounds__(QB)
void attn_kernel(const int* __restrict__ pos_ids)
{
    const int h  = blockIdx.y;
    const int qtile = gridDim.x - 1 - blockIdx.x;
    const int q0 = qtile * QB;
    const int q  = q0 + threadIdx.x;

    __shared__ float Ks[KB][HD];
    __shared__ float Vs[KB][HD];
    __shared__ float Kpos[KB];

    float qreg[HD];
    const float* qptr = g_q + ((size_t)h * S + q) * HD;
#pragma unroll
    for (int d = 0; d < HD; d++) qreg[d] = qptr[d] * SCALE;

    const float slope = exp2f(-0.25f * (float)(h + 1));
    const float posq  = (float)pos_ids[q];

    float m = -1e30f, l = 0.f;
    float acc[HD];
#pragma unroll
    for (int d = 0; d < HD; d++) acc[d] = 0.f;

    const int kend = q0 + QB;
    for (int kt = 0; kt < kend; kt += KB) {
        __syncthreads();
        const float* kp = g_k + ((size_t)h * S + kt) * HD;
        const float* vp = g_v + ((size_t)h * S + kt) * HD;
        for (int i = threadIdx.x; i < KB * HD; i += QB) {
            Ks[i / HD][i % HD] = kp[i];
            Vs[i / HD][i % HD] = vp[i];
        }
        if (threadIdx.x < KB) Kpos[threadIdx.x] = (float)pos_ids[kt + threadIdx.x];
        __syncthreads();

        int jmax = q - kt + 1;
        if (jmax > KB) jmax = KB;
        for (int j = 0; j < jmax; j++) {
            float sdot = 0.f;
#pragma unroll
            for (int d = 0; d < HD; d++) sdot = fmaf(qreg[d], Ks[j][d], sdot);
            float score = sdot + slope * (Kpos[j] - posq);
            if (score <= m) {
                float p = __expf(score - m);
                l += p;
#pragma unroll
                for (int d = 0; d < HD; d++) acc[d] = fmaf(p, Vs[j][d], acc[d]);
            } else {
                float corr = __expf(m - score);
                m = score;
                l = fmaf(l, corr, 1.f);
#pragma unroll
                for (int d = 0; d < HD; d++) acc[d] = fmaf(acc[d], corr, Vs[j][d]);
            }
        }
    }

    float invl = 1.f / l;
    float* op = g_attn + (size_t)q * HID + h * HD;
#pragma unroll
    for (int d = 0; d < HD; d++) op[d] = acc[d] * invl;
}

// ---------------- launch -------------------------------------------------------
extern "C" void kernel_launch(void* const* d_in, const int* in_sizes, int n_in,
                              void* d_out, int out_size)
{
    const int*   pos  = nullptr;
    const float* hs   = nullptr;
    const float* wqkv = nullptr;
    const float* wout = nullptr;
    for (int i = 0; i < n_in; i++) {
        switch (in_sizes[i]) {
            case S:           pos  = (const int*)d_in[i];   break;
            case S * HID:     hs   = (const float*)d_in[i]; break;
            case HID * N_QKV: wqkv = (const float*)d_in[i]; break;
            case HID * HID:   wout = (const float*)d_in[i]; break;
        }
    }
    if (!pos || !hs || !wqkv || !wout) return;

    cudaFuncSetAttribute(mma_gemm, cudaFuncAttributeMaxDynamicSharedMemorySize, GEMM_SMEM);

    __nv_bfloat16 *ahi, *alo, *wqh, *wql, *woh, *wol, *ath, *atl;
    float* attn_ptr;
    cudaGetSymbolAddress((void**)&ahi, g_a_hi);
    cudaGetSymbolAddress((void**)&alo, g_a_lo);
    cudaGetSymbolAddress((void**)&wqh, g_wqkv_hi);
    cudaGetSymbolAddress((void**)&wql, g_wqkv_lo);
    cudaGetSymbolAddress((void**)&woh, g_wout_hi);
    cudaGetSymbolAddress((void**)&wol, g_wout_lo);
    cudaGetSymbolAddress((void**)&ath, g_at_hi);
    cudaGetSymbolAddress((void**)&atl, g_at_lo);
    cudaGetSymbolAddress((void**)&attn_ptr, g_attn);

    // conversions
    conv_split<<<(S * HID) / 256, 256>>>(hs, ahi, alo, S * HID);
    convt_split<<<dim3(N_QKV / 32, HID / 32), dim3(32, 8)>>>(wqkv, wqh, wql, HID, N_QKV);
    convt_split<<<dim3(HID / 32, HID / 32), dim3(32, 8)>>>(wout, woh, wol, HID, HID);

    // 1) QKV projection (scatter epilogue into per-head q/k/v)
    mma_gemm<<<dim3(N_QKV / BNg, S / BMg), 256, GEMM_SMEM>>>(ahi, alo, wqh, wql, nullptr, HID, N_QKV, 1);

    // 2) RoPE
    rope_kernel<<<(NH * S * 32) / 256, 256>>>(pos);

    // 3) attention
    attn_kernel<<<dim3(S / QB, NH), QB>>>(pos);

    // 4) attn output -> bf16 split, then output projection
    conv_split<<<(S * HID) / 256, 256>>>(attn_ptr, ath, atl, S * HID);
    mma_gemm<<<dim3(HID / BNg, S / BMg), 256, GEMM_SMEM>>>(ath, atl, woh, wol, (float*)d_out, HID, HID, 0);
}

// round 4
// speedup vs baseline: 2.9055x; 1.9065x over previous
#include <cuda_runtime.h>
#include <cuda_bf16.h>
#include <cstdint>

// Problem constants
#define S    2048
#define HID  2560
#define NH   32
#define HD   80
#define N_QKV (3*HID)          // 7680
#define SCALE 0.11180339887498949f   // 80^-0.5

// ---------------- scratch (device globals; no allocs allowed) ---------------
__device__ float g_q[NH * S * HD];
__device__ float g_k[NH * S * HD];
__device__ float g_v[NH * S * HD];
__device__ float g_attn[S * HID];
__device__ float g_posf[S];

__device__ __nv_bfloat16 g_a_hi[S * HID],      g_a_lo[S * HID];        // hidden (M,K)
__device__ __nv_bfloat16 g_wqkv_hi[N_QKV*HID], g_wqkv_lo[N_QKV*HID];   // (N,K) transposed
__device__ __nv_bfloat16 g_wout_hi[HID*HID],   g_wout_lo[HID*HID];     // (N,K) transposed
__device__ __nv_bfloat16 g_at_hi[S * HID],     g_at_lo[S * HID];       // attn out (M,K)

__device__ __nv_bfloat16 g_qh[NH*S*HD], g_ql[NH*S*HD];
__device__ __nv_bfloat16 g_kh[NH*S*HD], g_kl[NH*S*HD];
__device__ __nv_bfloat16 g_vh[NH*S*HD], g_vl[NH*S*HD];

// ---------------- PTX helpers ------------------------------------------------
__device__ __forceinline__ uint32_t smem_u32(const void* p) {
    return (uint32_t)__cvta_generic_to_shared((void*)p);
}
__device__ __forceinline__ void cp16(uint32_t s, const void* g) {
    asm volatile("cp.async.cg.shared.global [%0], [%1], 16;" :: "r"(s), "l"(g) : "memory");
}
__device__ __forceinline__ void ldsm_x4(uint32_t* r, uint32_t addr) {
    asm volatile("ldmatrix.sync.aligned.m8n8.x4.shared.b16 {%0,%1,%2,%3}, [%4];"
                 : "=r"(r[0]), "=r"(r[1]), "=r"(r[2]), "=r"(r[3]) : "r"(addr));
}
__device__ __forceinline__ void ldsm_x4t(uint32_t* r, uint32_t addr) {
    asm volatile("ldmatrix.sync.aligned.m8n8.x4.trans.shared.b16 {%0,%1,%2,%3}, [%4];"
                 : "=r"(r[0]), "=r"(r[1]), "=r"(r[2]), "=r"(r[3]) : "r"(addr));
}
__device__ __forceinline__ void ldsm_x2(uint32_t* r, uint32_t addr) {
    asm volatile("ldmatrix.sync.aligned.m8n8.x2.shared.b16 {%0,%1}, [%2];"
                 : "=r"(r[0]), "=r"(r[1]) : "r"(addr));
}
__device__ __forceinline__ void mma16816(float* d, const uint32_t* a, const uint32_t* b) {
    asm volatile("mma.sync.aligned.m16n8k16.row.col.f32.bf16.bf16.f32 "
                 "{%0,%1,%2,%3}, {%4,%5,%6,%7}, {%8,%9}, {%0,%1,%2,%3};"
                 : "+f"(d[0]), "+f"(d[1]), "+f"(d[2]), "+f"(d[3])
                 : "r"(a[0]), "r"(a[1]), "r"(a[2]), "r"(a[3]), "r"(b[0]), "r"(b[1]));
}
__device__ __forceinline__ void split2(float a, float b, uint32_t& hi, uint32_t& lo) {
    __nv_bfloat162 h, l;
    h.x = __float2bfloat16(a);
    h.y = __float2bfloat16(b);
    l.x = __float2bfloat16(a - __bfloat162float(h.x));
    l.y = __float2bfloat16(b - __bfloat162float(h.y));
    hi = *(uint32_t*)&h;
    lo = *(uint32_t*)&l;
}

// ---------------- HMMA GEMM: D[M,N] = A[M,K] @ B[N,K]^T (bf16x3 split) ------
#define BMg 128
#define BNg 128
#define RSg 40                      // bf16 row stride (32 data + 8 pad)
#define TENg (128*RSg)              // bf16 elems per tensor tile (5120)
#define STAGEg (4*TENg)             // per stage (A_hi, A_lo, B_hi, B_lo)
#define GEMM_SMEM (2*STAGEg*2)      // bytes (81920)

__global__ __launch_bounds__(256)
void mma_gemm(const __nv_bfloat16* __restrict__ Ahi, const __nv_bfloat16* __restrict__ Alo,
              const __nv_bfloat16* __restrict__ Bhi, const __nv_bfloat16* __restrict__ Blo,
              float* __restrict__ C, int K, int N, int mode)
{
    extern __shared__ __align__(128) __nv_bfloat16 sm[];
    const int tid  = threadIdx.x;
    const int wid  = tid >> 5;
    const int lane = tid & 31;
    const int wr   = wid >> 2;
    const int wc   = wid & 3;
    const int rowBase = blockIdx.y * BMg;
    const int colBase = blockIdx.x * BNg;
    const uint32_t smbase = smem_u32(sm);

    float acc[4][4][4];
#pragma unroll
    for (int i = 0; i < 4; i++)
#pragma unroll
        for (int j = 0; j < 4; j++)
#pragma unroll
            for (int k = 0; k < 4; k++) acc[i][j][k] = 0.f;

    const int NC = K >> 5;

    {
#pragma unroll
        for (int t = 0; t < 2; t++) {
            int idx = tid + t * 256;
            int row = idx >> 2, seg = idx & 3;
            uint32_t so = smbase + (uint32_t)(row * RSg + seg * 8) * 2;
            size_t gA = (size_t)(rowBase + row) * K + seg * 8;
            size_t gB = (size_t)(colBase + row) * K + seg * 8;
            cp16(so,                Ahi + gA);
            cp16(so + TENg * 2,     Alo + gA);
            cp16(so + 2 * TENg * 2, Bhi + gB);
            cp16(so + 3 * TENg * 2, Blo + gB);
        }
        asm volatile("cp.async.commit_group;" ::: "memory");
    }

    for (int c = 0; c < NC; c++) {
        const int s = c & 1;
        if (c + 1 < NC) {
            const int kt = (c + 1) << 5;
            const uint32_t sb = smbase + ((c + 1) & 1) * STAGEg * 2;
#pragma unroll
            for (int t = 0; t < 2; t++) {
                int idx = tid + t * 256;
                int row = idx >> 2, seg = idx & 3;
                uint32_t so = sb + (uint32_t)(row * RSg + seg * 8) * 2;
                size_t gA = (size_t)(rowBase + row) * K + kt + seg * 8;
                size_t gB = (size_t)(colBase + row) * K + kt + seg * 8;
                cp16(so,                Ahi + gA);
                cp16(so + TENg * 2,     Alo + gA);
                cp16(so + 2 * TENg * 2, Bhi + gB);
                cp16(so + 3 * TENg * 2, Blo + gB);
            }
        }
        asm volatile("cp.async.commit_group;" ::: "memory");
        asm volatile("cp.async.wait_group 1;" ::: "memory");
        __syncthreads();

        const uint32_t sb = smbase + s * STAGEg * 2;
#pragma unroll
        for (int ks = 0; ks < 2; ks++) {
            const int kof = ks * 16;
            uint32_t ah[4][4], al[4][4];
#pragma unroll
            for (int mf = 0; mf < 4; mf++) {
                int row = wr * 64 + mf * 16 + (lane & 15);
                int col = kof + (lane >> 4) * 8;
                uint32_t ad = sb + (uint32_t)(row * RSg + col) * 2;
                ldsm_x4(ah[mf], ad);
                ldsm_x4(al[mf], ad + TENg * 2);
            }
            uint32_t bh[4][2], bl[4][2];
#pragma unroll
            for (int nf = 0; nf < 4; nf++) {
                int brow = wc * 32 + nf * 8 + (lane & 7);
                int bcol = kof + ((lane >> 3) & 1) * 8;
                uint32_t bd = sb + 2 * TENg * 2 + (uint32_t)(brow * RSg + bcol) * 2;
                ldsm_x2(bh[nf], bd);
                ldsm_x2(bl[nf], bd + TENg * 2);
            }
#pragma unroll
            for (int mf = 0; mf < 4; mf++)
#pragma unroll
                for (int nf = 0; nf < 4; nf++) {
                    mma16816(acc[mf][nf], ah[mf], bh[nf]);
                    mma16816(acc[mf][nf], ah[mf], bl[nf]);
                    mma16816(acc[mf][nf], al[mf], bh[nf]);
                }
        }
        __syncthreads();
    }

#pragma unroll
    for (int mf = 0; mf < 4; mf++) {
#pragma unroll
        for (int nf = 0; nf < 4; nf++) {
            int row = rowBase + wr * 64 + mf * 16 + (lane >> 2);
            int col = colBase + wc * 32 + nf * 8 + (lane & 3) * 2;
            if (mode == 0) {
                *(float2*)(C + (size_t)row * N + col) =
                    make_float2(acc[mf][nf][0], acc[mf][nf][1]);
                *(float2*)(C + (size_t)(row + 8) * N + col) =
                    make_float2(acc[mf][nf][2], acc[mf][nf][3]);
            } else {
                int p   = col / HID;
                int rem = col - p * HID;
                int h   = rem / HD;
                int d   = rem - h * HD;
                float* dst = (p == 0) ? g_q : ((p == 1) ? g_k : g_v);
                *(float2*)(&dst[((size_t)h * S + row) * HD + d]) =
                    make_float2(acc[mf][nf][0], acc[mf][nf][1]);
                *(float2*)(&dst[((size_t)h * S + row + 8) * HD + d]) =
                    make_float2(acc[mf][nf][2], acc[mf][nf][3]);
            }
        }
    }
}

// ---------------- conversions ------------------------------------------------
__global__ void conv_split(const float* __restrict__ x, __nv_bfloat16* __restrict__ hi,
                           __nv_bfloat16* __restrict__ lo, int n)
{
    int i = blockIdx.x * blockDim.x + threadIdx.x;
    if (i >= n) return;
    float v = x[i];
    __nv_bfloat16 h = __float2bfloat16(v);
    hi[i] = h;
    lo[i] = __float2bfloat16(v - __bfloat162float(h));
}

__global__ void convt_split(const float* __restrict__ W, __nv_bfloat16* __restrict__ hi,
                            __nv_bfloat16* __restrict__ lo, int K, int N)
{
    __shared__ float t[32][33];
    int n0 = blockIdx.x * 32, k0 = blockIdx.y * 32;
    for (int r = threadIdx.y; r < 32; r += 8)
        t[r][threadIdx.x] = W[(size_t)(k0 + r) * N + n0 + threadIdx.x];
    __syncthreads();
    for (int r = threadIdx.y; r < 32; r += 8) {
        float v = t[threadIdx.x][r];
        __nv_bfloat16 h = __float2bfloat16(v);
        size_t o = (size_t)(n0 + r) * K + k0 + threadIdx.x;
        hi[o] = h;
        lo[o] = __float2bfloat16(v - __bfloat162float(h));
    }
}

// split q/k/v (post-rope) into bf16 hi/lo; also pos -> float
__global__ void conv_qkv(const int* __restrict__ pos)
{
    int i = blockIdx.x * blockDim.x + threadIdx.x;
    if (i < S) g_posf[i] = (float)pos[i];
    if (i >= NH * S * HD) return;
    float q = g_q[i];
    __nv_bfloat16 qh = __float2bfloat16(q);
    g_qh[i] = qh; g_ql[i] = __float2bfloat16(q - __bfloat162float(qh));
    float k = g_k[i];
    __nv_bfloat16 kh = __float2bfloat16(k);
    g_kh[i] = kh; g_kl[i] = __float2bfloat16(k - __bfloat162float(kh));
    float v = g_v[i];
    __nv_bfloat16 vh = __float2bfloat16(v);
    g_vh[i] = vh; g_vl[i] = __float2bfloat16(v - __bfloat162float(vh));
}

// ---------------- RoPE --------------------------------------------------------
__global__ void rope_kernel(const int* __restrict__ pos_ids)
{
    int idx = blockIdx.x * blockDim.x + threadIdx.x;
    int d = idx & 31;
    int s = (idx >> 5) & (S - 1);
    int h = idx >> 16;
    if (h >= NH) return;

    float posf = (float)pos_ids[s];
    float inv  = exp2f(-0.415241011861f * (float)d);
    float ang  = posf * inv;
    float c, sn;
    sincosf(ang, &sn, &c);

    size_t base = ((size_t)h * S + s) * HD;
    float q1 = g_q[base + d], q2 = g_q[base + d + 32];
    g_q[base + d]      = q1 * c - q2 * sn;
    g_q[base + d + 32] = q2 * c + q1 * sn;
    float k1 = g_k[base + d], k2 = g_k[base + d + 32];
    g_k[base + d]      = k1 * c - k2 * sn;
    g_k[base + d + 32] = k2 * c + k1 * sn;
}

// ---------------- HMMA flash attention with ALiBi ----------------------------
#define AQB 128
#define AKB 64
#define ARS 88                          // padded row stride (bf16)
#define T_ELEMS (AKB*ARS)               // 5632
#define KPOS_OFF (4*T_ELEMS*2)          // 45056
#define ASTAGE (KPOS_OFF + 256)         // 45312 (128-aligned)
#define ATTN_SMEM (2*ASTAGE)            // 90624

__global__ __launch_bounds__(256)
void attn_mma()
{
    extern __shared__ char smbuf[];
    const int h     = blockIdx.y;
    const int qtile = gridDim.x - 1 - blockIdx.x;
    const int q0    = qtile * AQB;
    const int tid   = threadIdx.x;
    const int wid   = tid >> 5;
    const int lane  = tid & 31;
    const uint32_t sb = smem_u32(smbuf);

    // Q fragments (registers, whole kernel)
    const int r0 = q0 + wid * 16 + (lane >> 2);     // global q row (and +8)
    const int cp = (lane & 3) * 2;
    uint32_t qfh[5][4], qfl[5][4];
    {
        const __nv_bfloat16* qhp = g_qh + ((size_t)h * S + r0) * HD;
        const __nv_bfloat16* qlp = g_ql + ((size_t)h * S + r0) * HD;
#pragma unroll
        for (int ks = 0; ks < 5; ks++) {
            int c = ks * 16 + cp;
            qfh[ks][0] = *(const uint32_t*)(qhp + c);
            qfh[ks][1] = *(const uint32_t*)(qhp + 8 * HD + c);
            qfh[ks][2] = *(const uint32_t*)(qhp + c + 8);
            qfh[ks][3] = *(const uint32_t*)(qhp + 8 * HD + c + 8);
            qfl[ks][0] = *(const uint32_t*)(qlp + c);
            qfl[ks][1] = *(const uint32_t*)(qlp + 8 * HD + c);
            qfl[ks][2] = *(const uint32_t*)(qlp + c + 8);
            qfl[ks][3] = *(const uint32_t*)(qlp + 8 * HD + c + 8);
        }
    }
    const float qp0 = g_posf[r0];
    const float qp1 = g_posf[r0 + 8];
    const float slope = exp2f(-0.25f * (float)(h + 1));

    float o[10][4];
#pragma unroll
    for (int i = 0; i < 10; i++)
#pragma unroll
        for (int j = 0; j < 4; j++) o[i][j] = 0.f;
    float m0 = -1e30f, m1 = -1e30f, l0 = 0.f, l1 = 0.f;

    const int NT = (q0 + AQB) / AKB;

    auto issue = [&](int t) {
        const uint32_t dst = sb + (t & 1) * ASTAGE;
        const int kt = t * AKB;
#pragma unroll
        for (int it = 0; it < 10; it++) {
            int idx = it * 256 + tid;            // 0..2559
            int tensor = idx / 640;
            int rem = idx - tensor * 640;
            int row = rem / 10, seg = rem - row * 10;
            const __nv_bfloat16* base =
                (tensor == 0) ? g_kh : (tensor == 1) ? g_kl : (tensor == 2) ? g_vh : g_vl;
            const __nv_bfloat16* src = base + ((size_t)h * S + kt + row) * HD + seg * 8;
            cp16(dst + (uint32_t)tensor * (T_ELEMS * 2) + (uint32_t)(row * ARS + seg * 8) * 2, src);
        }
        if (tid < 16) cp16(dst + KPOS_OFF + tid * 16, g_posf + kt + tid * 4);
    };

    issue(0);
    asm volatile("cp.async.commit_group;" ::: "memory");

    for (int t = 0; t < NT; t++) {
        if (t + 1 < NT) issue(t + 1);
        asm volatile("cp.async.commit_group;" ::: "memory");
        asm volatile("cp.async.wait_group 1;" ::: "memory");
        __syncthreads();

        const uint32_t st = sb + (t & 1) * ASTAGE;
        const float* kposb = (const float*)(smbuf + (t & 1) * ASTAGE + KPOS_OFF);

        // ---- S = Q K^T  (bf16x3) ----
        float accs[8][4];
#pragma unroll
        for (int nf = 0; nf < 8; nf++)
#pragma unroll
            for (int e = 0; e < 4; e++) accs[nf][e] = 0.f;

        const int mq = lane >> 3;                 // 0..3 matrix index for ldsm_x4
#pragma unroll
        for (int ks = 0; ks < 5; ks++) {
#pragma unroll
            for (int nfp = 0; nfp < 4; nfp++) {
                uint32_t bh[4], bl[4];
                uint32_t row = (uint32_t)((nfp * 2 + (mq >> 1)) * 8 + (lane & 7));
                uint32_t col = (uint32_t)(ks * 16 + (mq & 1) * 8);
                uint32_t ad = st + (row * ARS + col) * 2;
                ldsm_x4(bh, ad);
                ldsm_x4(bl, ad + T_ELEMS * 2);
                mma16816(accs[nfp*2],   qfh[ks], &bh[0]);
                mma16816(accs[nfp*2],   qfh[ks], &bl[0]);
                mma16816(accs[nfp*2],   qfl[ks], &bh[0]);
                mma16816(accs[nfp*2+1], qfh[ks], &bh[2]);
                mma16816(accs[nfp*2+1], qfh[ks], &bl[2]);
                mma16816(accs[nfp*2+1], qfl[ks], &bh[2]);
            }
        }

        // ---- masked/biased softmax (online) ----
        float mx0 = -1e30f, mx1 = -1e30f;
#pragma unroll
        for (int nf = 0; nf < 8; nf++) {
            float2 kc = *(const float2*)(kposb + nf * 8 + cp);
            float b0 = slope * kc.x, b1 = slope * kc.y;
            float s0 = (kc.x <= qp0) ? fmaf(accs[nf][0], SCALE, b0) : -1e30f;
            float s1 = (kc.y <= qp0) ? fmaf(accs[nf][1], SCALE, b1) : -1e30f;
            float s2 = (kc.x <= qp1) ? fmaf(accs[nf][2], SCALE, b0) : -1e30f;
            float s3 = (kc.y <= qp1) ? fmaf(accs[nf][3], SCALE, b1) : -1e30f;
            accs[nf][0] = s0; accs[nf][1] = s1; accs[nf][2] = s2; accs[nf][3] = s3;
            mx0 = fmaxf(mx0, fmaxf(s0, s1));
            mx1 = fmaxf(mx1, fmaxf(s2, s3));
        }
        mx0 = fmaxf(mx0, __shfl_xor_sync(0xFFFFFFFFu, mx0, 1));
        mx0 = fmaxf(mx0, __shfl_xor_sync(0xFFFFFFFFu, mx0, 2));
        mx1 = fmaxf(mx1, __shfl_xor_sync(0xFFFFFFFFu, mx1, 1));
        mx1 = fmaxf(mx1, __shfl_xor_sync(0xFFFFFFFFu, mx1, 2));

        float m0n = fmaxf(m0, mx0), m1n = fmaxf(m1, mx1);
        float c0 = __expf(m0 - m0n), c1 = __expf(m1 - m1n);
        m0 = m0n; m1 = m1n;

        float sum0 = 0.f, sum1 = 0.f;
#pragma unroll
        for (int nf = 0; nf < 8; nf++) {
            float p0 = __expf(accs[nf][0] - m0);
            float p1 = __expf(accs[nf][1] - m0);
            float p2 = __expf(accs[nf][2] - m1);
            float p3 = __expf(accs[nf][3] - m1);
            accs[nf][0] = p0; accs[nf][1] = p1; accs[nf][2] = p2; accs[nf][3] = p3;
            sum0 += p0 + p1; sum1 += p2 + p3;
        }
        l0 = l0 * c0 + sum0;
        l1 = l1 * c1 + sum1;
#pragma unroll
        for (int nf = 0; nf < 10; nf++) {
            o[nf][0] *= c0; o[nf][1] *= c0;
            o[nf][2] *= c1; o[nf][3] *= c1;
        }

        // ---- P fragments (hi/lo) ----
        uint32_t ph[4][4], pl[4][4];
#pragma unroll
        for (int ks2 = 0; ks2 < 4; ks2++) {
            split2(accs[2*ks2][0],   accs[2*ks2][1],   ph[ks2][0], pl[ks2][0]);
            split2(accs[2*ks2][2],   accs[2*ks2][3],   ph[ks2][1], pl[ks2][1]);
            split2(accs[2*ks2+1][0], accs[2*ks2+1][1], ph[ks2][2], pl[ks2][2]);
            split2(accs[2*ks2+1][2], accs[2*ks2+1][3], ph[ks2][3], pl[ks2][3]);
        }

        // ---- O += P V  (bf16x3) ----
#pragma unroll
        for (int ks2 = 0; ks2 < 4; ks2++) {
#pragma unroll
            for (int nfp = 0; nfp < 5; nfp++) {
                uint32_t bvh[4], bvl[4];
                uint32_t row = (uint32_t)(ks2 * 16 + (mq & 1) * 8 + (lane & 7));
                uint32_t col = (uint32_t)((nfp * 2 + (mq >> 1)) * 8);
                uint32_t ad = st + 2 * (T_ELEMS * 2) + (row * ARS + col) * 2;
                ldsm_x4t(bvh, ad);
                ldsm_x4t(bvl, ad + T_ELEMS * 2);
                mma16816(o[nfp*2],   ph[ks2], &bvh[0]);
                mma16816(o[nfp*2],   ph[ks2], &bvl[0]);
                mma16816(o[nfp*2],   pl[ks2], &bvh[0]);
                mma16816(o[nfp*2+1], ph[ks2], &bvh[2]);
                mma16816(o[nfp*2+1], ph[ks2], &bvl[2]);
                mma16816(o[nfp*2+1], pl[ks2], &bvh[2]);
            }
        }
        __syncthreads();
    }

    // ---- epilogue ----
    l0 += __shfl_xor_sync(0xFFFFFFFFu, l0, 1);
    l0 += __shfl_xor_sync(0xFFFFFFFFu, l0, 2);
    l1 += __shfl_xor_sync(0xFFFFFFFFu, l1, 1);
    l1 += __shfl_xor_sync(0xFFFFFFFFu, l1, 2);
    float inv0 = 1.f / l0, inv1 = 1.f / l1;

    float* op0 = g_attn + (size_t)r0 * HID + h * HD;
#pragma unroll
    for (int nf = 0; nf < 10; nf++) {
        int col = nf * 8 + cp;
        *(float2*)(op0 + col)           = make_float2(o[nf][0] * inv0, o[nf][1] * inv0);
        *(float2*)(op0 + 8 * HID + col) = make_float2(o[nf][2] * inv1, o[nf][3] * inv1);
    }
}

// ---------------- launch -------------------------------------------------------
extern "C" void kernel_launch(void* const* d_in, const int* in_sizes, int n_in,
                              void* d_out, int out_size)
{
    const int*   pos  = nullptr;
    const float* hs   = nullptr;
    const float* wqkv = nullptr;
    const float* wout = nullptr;
    for (int i = 0; i < n_in; i++) {
        switch (in_sizes[i]) {
            case S:           pos  = (const int*)d_in[i];   break;
            case S * HID:     hs   = (const float*)d_in[i]; break;
            case HID * N_QKV: wqkv = (const float*)d_in[i]; break;
            case HID * HID:   wout = (const float*)d_in[i]; break;
        }
    }
    if (!pos || !hs || !wqkv || !wout) return;

    cudaFuncSetAttribute(mma_gemm, cudaFuncAttributeMaxDynamicSharedMemorySize, GEMM_SMEM);
    cudaFuncSetAttribute(attn_mma, cudaFuncAttributeMaxDynamicSharedMemorySize, ATTN_SMEM);

    __nv_bfloat16 *ahi, *alo, *wqh, *wql, *woh, *wol, *ath, *atl;
    float* attn_ptr;
    cudaGetSymbolAddress((void**)&ahi, g_a_hi);
    cudaGetSymbolAddress((void**)&alo, g_a_lo);
    cudaGetSymbolAddress((void**)&wqh, g_wqkv_hi);
    cudaGetSymbolAddress((void**)&wql, g_wqkv_lo);
    cudaGetSymbolAddress((void**)&woh, g_wout_hi);
    cudaGetSymbolAddress((void**)&wol, g_wout_lo);
    cudaGetSymbolAddress((void**)&ath, g_at_hi);
    cudaGetSymbolAddress((void**)&atl, g_at_lo);
    cudaGetSymbolAddress((void**)&attn_ptr, g_attn);

    // conversions
    conv_split<<<(S * HID) / 256, 256>>>(hs, ahi, alo, S * HID);
    convt_split<<<dim3(N_QKV / 32, HID / 32), dim3(32, 8)>>>(wqkv, wqh, wql, HID, N_QKV);
    convt_split<<<dim3(HID / 32, HID / 32), dim3(32, 8)>>>(wout, woh, wol, HID, HID);

    // 1) QKV projection (scatter epilogue into per-head q/k/v, fp32)
    mma_gemm<<<dim3(N_QKV / BNg, S / BMg), 256, GEMM_SMEM>>>(ahi, alo, wqh, wql, nullptr, HID, N_QKV, 1);

    // 2) RoPE (fp32 in-place)
    rope_kernel<<<(NH * S * 32) / 256, 256>>>(pos);

    // 3) q/k/v -> bf16 hi/lo (+ pos -> float)
    conv_qkv<<<(NH * S * HD) / 256, 256>>>(pos);

    // 4) flash attention (HMMA)
    attn_mma<<<dim3(S / AQB, NH), 256, ATTN_SMEM>>>();

    // 5) attn output -> bf16 split, then output projection
    conv_split<<<(S * HID) / 256, 256>>>(attn_ptr, ath, atl, S * HID);
    mma_gemm<<<dim3(HID / BNg, S / BMg), 256, GEMM_SMEM>>>(ath, atl, woh, wol, (float*)d_out, HID, HID, 0);
}

// round 5
// speedup vs baseline: 2.9205x; 1.0052x over previous
#include <cuda_runtime.h>
#include <cuda_bf16.h>
#include <cstdint>

// Problem constants
#define S    2048
#define HID  2560
#define NH   32
#define HD   80
#define N_QKV (3*HID)          // 7680
#define SCALE 0.11180339887498949f   // 80^-0.5

// ---------------- scratch (device globals; no allocs allowed) ---------------
__device__ float g_q[NH * S * HD];
__device__ float g_k[NH * S * HD];
__device__ float g_v[NH * S * HD];
__device__ float g_attn[S * HID];
__device__ float g_posf[S];

__device__ __nv_bfloat16 g_a_hi[S * HID],      g_a_lo[S * HID];        // hidden (M,K)
__device__ __nv_bfloat16 g_wqkv_hi[N_QKV*HID], g_wqkv_lo[N_QKV*HID];   // (N,K) transposed
__device__ __nv_bfloat16 g_wout_hi[HID*HID],   g_wout_lo[HID*HID];     // (N,K) transposed
__device__ __nv_bfloat16 g_at_hi[S * HID],     g_at_lo[S * HID];       // attn out (M,K)

__device__ __nv_bfloat16 g_qh[NH*S*HD], g_ql[NH*S*HD];
__device__ __nv_bfloat16 g_kh[NH*S*HD], g_kl[NH*S*HD];
__device__ __nv_bfloat16 g_vh[NH*S*HD], g_vl[NH*S*HD];

// ---------------- PTX helpers ------------------------------------------------
__device__ __forceinline__ uint32_t smem_u32(const void* p) {
    return (uint32_t)__cvta_generic_to_shared((void*)p);
}
__device__ __forceinline__ void cp16(uint32_t s, const void* g) {
    asm volatile("cp.async.cg.shared.global [%0], [%1], 16;" :: "r"(s), "l"(g) : "memory");
}
__device__ __forceinline__ void ldsm_x4(uint32_t* r, uint32_t addr) {
    asm volatile("ldmatrix.sync.aligned.m8n8.x4.shared.b16 {%0,%1,%2,%3}, [%4];"
                 : "=r"(r[0]), "=r"(r[1]), "=r"(r[2]), "=r"(r[3]) : "r"(addr));
}
__device__ __forceinline__ void ldsm_x4t(uint32_t* r, uint32_t addr) {
    asm volatile("ldmatrix.sync.aligned.m8n8.x4.trans.shared.b16 {%0,%1,%2,%3}, [%4];"
                 : "=r"(r[0]), "=r"(r[1]), "=r"(r[2]), "=r"(r[3]) : "r"(addr));
}
__device__ __forceinline__ void ldsm_x2(uint32_t* r, uint32_t addr) {
    asm volatile("ldmatrix.sync.aligned.m8n8.x2.shared.b16 {%0,%1}, [%2];"
                 : "=r"(r[0]), "=r"(r[1]) : "r"(addr));
}
__device__ __forceinline__ void mma16816(float* d, const uint32_t* a, const uint32_t* b) {
    asm volatile("mma.sync.aligned.m16n8k16.row.col.f32.bf16.bf16.f32 "
                 "{%0,%1,%2,%3}, {%4,%5,%6,%7}, {%8,%9}, {%0,%1,%2,%3};"
                 : "+f"(d[0]), "+f"(d[1]), "+f"(d[2]), "+f"(d[3])
                 : "r"(a[0]), "r"(a[1]), "r"(a[2]), "r"(a[3]), "r"(b[0]), "r"(b[1]));
}
__device__ __forceinline__ void split2(float a, float b, uint32_t& hi, uint32_t& lo) {
    __nv_bfloat162 h, l;
    h.x = __float2bfloat16(a);
    h.y = __float2bfloat16(b);
    l.x = __float2bfloat16(a - __bfloat162float(h.x));
    l.y = __float2bfloat16(b - __bfloat162float(h.y));
    hi = *(uint32_t*)&h;
    lo = *(uint32_t*)&l;
}

// ---------------- HMMA GEMM: D[M,N] = A[M,K] @ B[N,K]^T (bf16x3 split) ------
#define BMg 128
#define BNg 128
#define RSg 40                      // bf16 row stride (32 data + 8 pad)
#define TENg (128*RSg)              // bf16 elems per tensor tile (5120)
#define STAGEg (4*TENg)             // per stage (A_hi, A_lo, B_hi, B_lo)
#define GEMM_SMEM (2*STAGEg*2)      // bytes (81920)

__global__ __launch_bounds__(256)
void mma_gemm(const __nv_bfloat16* __restrict__ Ahi, const __nv_bfloat16* __restrict__ Alo,
              const __nv_bfloat16* __restrict__ Bhi, const __nv_bfloat16* __restrict__ Blo,
              float* __restrict__ C, int K, int N, int mode)
{
    extern __shared__ __align__(128) __nv_bfloat16 sm[];
    const int tid  = threadIdx.x;
    const int wid  = tid >> 5;
    const int lane = tid & 31;
    const int wr   = wid >> 2;
    const int wc   = wid & 3;
    const int rowBase = blockIdx.y * BMg;
    const int colBase = blockIdx.x * BNg;
    const uint32_t smbase = smem_u32(sm);

    float acc[4][4][4];
#pragma unroll
    for (int i = 0; i < 4; i++)
#pragma unroll
        for (int j = 0; j < 4; j++)
#pragma unroll
            for (int k = 0; k < 4; k++) acc[i][j][k] = 0.f;

    const int NC = K >> 5;

    {
#pragma unroll
        for (int t = 0; t < 2; t++) {
            int idx = tid + t * 256;
            int row = idx >> 2, seg = idx & 3;
            uint32_t so = smbase + (uint32_t)(row * RSg + seg * 8) * 2;
            size_t gA = (size_t)(rowBase + row) * K + seg * 8;
            size_t gB = (size_t)(colBase + row) * K + seg * 8;
            cp16(so,                Ahi + gA);
            cp16(so + TENg * 2,     Alo + gA);
            cp16(so + 2 * TENg * 2, Bhi + gB);
            cp16(so + 3 * TENg * 2, Blo + gB);
        }
        asm volatile("cp.async.commit_group;" ::: "memory");
    }

    for (int c = 0; c < NC; c++) {
        const int s = c & 1;
        if (c + 1 < NC) {
            const int kt = (c + 1) << 5;
            const uint32_t sb = smbase + ((c + 1) & 1) * STAGEg * 2;
#pragma unroll
            for (int t = 0; t < 2; t++) {
                int idx = tid + t * 256;
                int row = idx >> 2, seg = idx & 3;
                uint32_t so = sb + (uint32_t)(row * RSg + seg * 8) * 2;
                size_t gA = (size_t)(rowBase + row) * K + kt + seg * 8;
                size_t gB = (size_t)(colBase + row) * K + kt + seg * 8;
                cp16(so,                Ahi + gA);
                cp16(so + TENg * 2,     Alo + gA);
                cp16(so + 2 * TENg * 2, Bhi + gB);
                cp16(so + 3 * TENg * 2, Blo + gB);
            }
        }
        asm volatile("cp.async.commit_group;" ::: "memory");
        asm volatile("cp.async.wait_group 1;" ::: "memory");
        __syncthreads();

        const uint32_t sb = smbase + s * STAGEg * 2;
#pragma unroll
        for (int ks = 0; ks < 2; ks++) {
            const int kof = ks * 16;
            uint32_t ah[4][4], al[4][4];
#pragma unroll
            for (int mf = 0; mf < 4; mf++) {
                int row = wr * 64 + mf * 16 + (lane & 15);
                int col = kof + (lane >> 4) * 8;
                uint32_t ad = sb + (uint32_t)(row * RSg + col) * 2;
                ldsm_x4(ah[mf], ad);
                ldsm_x4(al[mf], ad + TENg * 2);
            }
            uint32_t bh[4][2], bl[4][2];
#pragma unroll
            for (int nf = 0; nf < 4; nf++) {
                int brow = wc * 32 + nf * 8 + (lane & 7);
                int bcol = kof + ((lane >> 3) & 1) * 8;
                uint32_t bd = sb + 2 * TENg * 2 + (uint32_t)(brow * RSg + bcol) * 2;
                ldsm_x2(bh[nf], bd);
                ldsm_x2(bl[nf], bd + TENg * 2);
            }
            // three passes over 16 independent accumulators: no RAW chains
#pragma unroll
            for (int mf = 0; mf < 4; mf++)
#pragma unroll
                for (int nf = 0; nf < 4; nf++)
                    mma16816(acc[mf][nf], ah[mf], bh[nf]);
#pragma unroll
            for (int mf = 0; mf < 4; mf++)
#pragma unroll
                for (int nf = 0; nf < 4; nf++)
                    mma16816(acc[mf][nf], ah[mf], bl[nf]);
#pragma unroll
            for (int mf = 0; mf < 4; mf++)
#pragma unroll
                for (int nf = 0; nf < 4; nf++)
                    mma16816(acc[mf][nf], al[mf], bh[nf]);
        }
        __syncthreads();
    }

#pragma unroll
    for (int mf = 0; mf < 4; mf++) {
#pragma unroll
        for (int nf = 0; nf < 4; nf++) {
            int row = rowBase + wr * 64 + mf * 16 + (lane >> 2);
            int col = colBase + wc * 32 + nf * 8 + (lane & 3) * 2;
            if (mode == 0) {
                *(float2*)(C + (size_t)row * N + col) =
                    make_float2(acc[mf][nf][0], acc[mf][nf][1]);
                *(float2*)(C + (size_t)(row + 8) * N + col) =
                    make_float2(acc[mf][nf][2], acc[mf][nf][3]);
            } else {
                int p   = col / HID;
                int rem = col - p * HID;
                int h   = rem / HD;
                int d   = rem - h * HD;
                float* dst = (p == 0) ? g_q : ((p == 1) ? g_k : g_v);
                *(float2*)(&dst[((size_t)h * S + row) * HD + d]) =
                    make_float2(acc[mf][nf][0], acc[mf][nf][1]);
                *(float2*)(&dst[((size_t)h * S + row + 8) * HD + d]) =
                    make_float2(acc[mf][nf][2], acc[mf][nf][3]);
            }
        }
    }
}

// ---------------- conversions ------------------------------------------------
__global__ void conv_split(const float* __restrict__ x, __nv_bfloat16* __restrict__ hi,
                           __nv_bfloat16* __restrict__ lo, int n)
{
    int i = blockIdx.x * blockDim.x + threadIdx.x;
    if (i >= n) return;
    float v = x[i];
    __nv_bfloat16 h = __float2bfloat16(v);
    hi[i] = h;
    lo[i] = __float2bfloat16(v - __bfloat162float(h));
}

__global__ void convt_split(const float* __restrict__ W, __nv_bfloat16* __restrict__ hi,
                            __nv_bfloat16* __restrict__ lo, int K, int N)
{
    __shared__ float t[32][33];
    int n0 = blockIdx.x * 32, k0 = blockIdx.y * 32;
    for (int r = threadIdx.y; r < 32; r += 8)
        t[r][threadIdx.x] = W[(size_t)(k0 + r) * N + n0 + threadIdx.x];
    __syncthreads();
    for (int r = threadIdx.y; r < 32; r += 8) {
        float v = t[threadIdx.x][r];
        __nv_bfloat16 h = __float2bfloat16(v);
        size_t o = (size_t)(n0 + r) * K + k0 + threadIdx.x;
        hi[o] = h;
        lo[o] = __float2bfloat16(v - __bfloat162float(h));
    }
}

// split q/k/v (post-rope) into bf16 hi/lo; also pos -> float
__global__ void conv_qkv(const int* __restrict__ pos)
{
    int i = blockIdx.x * blockDim.x + threadIdx.x;
    if (i < S) g_posf[i] = (float)pos[i];
    if (i >= NH * S * HD) return;
    float q = g_q[i];
    __nv_bfloat16 qh = __float2bfloat16(q);
    g_qh[i] = qh; g_ql[i] = __float2bfloat16(q - __bfloat162float(qh));
    float k = g_k[i];
    __nv_bfloat16 kh = __float2bfloat16(k);
    g_kh[i] = kh; g_kl[i] = __float2bfloat16(k - __bfloat162float(kh));
    float v = g_v[i];
    __nv_bfloat16 vh = __float2bfloat16(v);
    g_vh[i] = vh; g_vl[i] = __float2bfloat16(v - __bfloat162float(vh));
}

// ---------------- RoPE --------------------------------------------------------
__global__ void rope_kernel(const int* __restrict__ pos_ids)
{
    int idx = blockIdx.x * blockDim.x + threadIdx.x;
    int d = idx & 31;
    int s = (idx >> 5) & (S - 1);
    int h = idx >> 16;
    if (h >= NH) return;

    float posf = (float)pos_ids[s];
    float inv  = exp2f(-0.415241011861f * (float)d);
    float ang  = posf * inv;
    float c, sn;
    sincosf(ang, &sn, &c);

    size_t base = ((size_t)h * S + s) * HD;
    float q1 = g_q[base + d], q2 = g_q[base + d + 32];
    g_q[base + d]      = q1 * c - q2 * sn;
    g_q[base + d + 32] = q2 * c + q1 * sn;
    float k1 = g_k[base + d], k2 = g_k[base + d + 32];
    g_k[base + d]      = k1 * c - k2 * sn;
    g_k[base + d + 32] = k2 * c + k1 * sn;
}

// ---------------- HMMA flash attention with ALiBi ----------------------------
#define AQB 128
#define AKB 64
#define ARS 88                          // padded row stride (bf16)
#define T_ELEMS (AKB*ARS)               // 5632
#define KPOS_OFF (4*T_ELEMS*2)          // 45056
#define ASTAGE (KPOS_OFF + 256)         // 45312 (128-aligned)
#define ATTN_SMEM (2*ASTAGE)            // 90624

__global__ __launch_bounds__(256)
void attn_mma()
{
    extern __shared__ char smbuf[];
    const int h     = blockIdx.y;
    const int qtile = gridDim.x - 1 - blockIdx.x;
    const int q0    = qtile * AQB;
    const int tid   = threadIdx.x;
    const int wid   = tid >> 5;
    const int lane  = tid & 31;
    const uint32_t sb = smem_u32(smbuf);

    // Q fragments (registers, whole kernel)
    const int r0 = q0 + wid * 16 + (lane >> 2);     // global q row (and +8)
    const int cp = (lane & 3) * 2;
    uint32_t qfh[5][4], qfl[5][4];
    {
        const __nv_bfloat16* qhp = g_qh + ((size_t)h * S + r0) * HD;
        const __nv_bfloat16* qlp = g_ql + ((size_t)h * S + r0) * HD;
#pragma unroll
        for (int ks = 0; ks < 5; ks++) {
            int c = ks * 16 + cp;
            qfh[ks][0] = *(const uint32_t*)(qhp + c);
            qfh[ks][1] = *(const uint32_t*)(qhp + 8 * HD + c);
            qfh[ks][2] = *(const uint32_t*)(qhp + c + 8);
            qfh[ks][3] = *(const uint32_t*)(qhp + 8 * HD + c + 8);
            qfl[ks][0] = *(const uint32_t*)(qlp + c);
            qfl[ks][1] = *(const uint32_t*)(qlp + 8 * HD + c);
            qfl[ks][2] = *(const uint32_t*)(qlp + c + 8);
            qfl[ks][3] = *(const uint32_t*)(qlp + 8 * HD + c + 8);
        }
    }
    const float qp0 = g_posf[r0];
    const float qp1 = g_posf[r0 + 8];
    const float slope = exp2f(-0.25f * (float)(h + 1));

    float o[10][4];
#pragma unroll
    for (int i = 0; i < 10; i++)
#pragma unroll
        for (int j = 0; j < 4; j++) o[i][j] = 0.f;
    float m0 = -1e30f, m1 = -1e30f, l0 = 0.f, l1 = 0.f;

    const int NT = (q0 + AQB) / AKB;

    auto issue = [&](int t) {
        const uint32_t dst = sb + (t & 1) * ASTAGE;
        const int kt = t * AKB;
#pragma unroll
        for (int it = 0; it < 10; it++) {
            int idx = it * 256 + tid;            // 0..2559
            int tensor = idx / 640;
            int rem = idx - tensor * 640;
            int row = rem / 10, seg = rem - row * 10;
            const __nv_bfloat16* base =
                (tensor == 0) ? g_kh : (tensor == 1) ? g_kl : (tensor == 2) ? g_vh : g_vl;
            const __nv_bfloat16* src = base + ((size_t)h * S + kt + row) * HD + seg * 8;
            cp16(dst + (uint32_t)tensor * (T_ELEMS * 2) + (uint32_t)(row * ARS + seg * 8) * 2, src);
        }
        if (tid < 16) cp16(dst + KPOS_OFF + tid * 16, g_posf + kt + tid * 4);
    };

    issue(0);
    asm volatile("cp.async.commit_group;" ::: "memory");

    for (int t = 0; t < NT; t++) {
        if (t + 1 < NT) issue(t + 1);
        asm volatile("cp.async.commit_group;" ::: "memory");
        asm volatile("cp.async.wait_group 1;" ::: "memory");
        __syncthreads();

        const uint32_t st = sb + (t & 1) * ASTAGE;
        const float* kposb = (const float*)(smbuf + (t & 1) * ASTAGE + KPOS_OFF);

        // ---- S = Q K^T  (bf16x3, pass-reordered) ----
        float accs[8][4];
#pragma unroll
        for (int nf = 0; nf < 8; nf++)
#pragma unroll
            for (int e = 0; e < 4; e++) accs[nf][e] = 0.f;

        const int mq = lane >> 3;                 // 0..3 matrix index for ldsm_x4
#pragma unroll
        for (int ks = 0; ks < 5; ks++) {
            uint32_t bh[4][4], bl[4][4];
#pragma unroll
            for (int nfp = 0; nfp < 4; nfp++) {
                uint32_t row = (uint32_t)((nfp * 2 + (mq >> 1)) * 8 + (lane & 7));
                uint32_t col = (uint32_t)(ks * 16 + (mq & 1) * 8);
                uint32_t ad = st + (row * ARS + col) * 2;
                ldsm_x4(bh[nfp], ad);
                ldsm_x4(bl[nfp], ad + T_ELEMS * 2);
            }
#pragma unroll
            for (int nfp = 0; nfp < 4; nfp++) {
                mma16816(accs[nfp*2],   qfh[ks], &bh[nfp][0]);
                mma16816(accs[nfp*2+1], qfh[ks], &bh[nfp][2]);
            }
#pragma unroll
            for (int nfp = 0; nfp < 4; nfp++) {
                mma16816(accs[nfp*2],   qfh[ks], &bl[nfp][0]);
                mma16816(accs[nfp*2+1], qfh[ks], &bl[nfp][2]);
            }
#pragma unroll
            for (int nfp = 0; nfp < 4; nfp++) {
                mma16816(accs[nfp*2],   qfl[ks], &bh[nfp][0]);
                mma16816(accs[nfp*2+1], qfl[ks], &bh[nfp][2]);
            }
        }

        // ---- masked/biased softmax (online) ----
        float mx0 = -1e30f, mx1 = -1e30f;
#pragma unroll
        for (int nf = 0; nf < 8; nf++) {
            float2 kc = *(const float2*)(kposb + nf * 8 + cp);
            float b0 = slope * kc.x, b1 = slope * kc.y;
            float s0 = (kc.x <= qp0) ? fmaf(accs[nf][0], SCALE, b0) : -1e30f;
            float s1 = (kc.y <= qp0) ? fmaf(accs[nf][1], SCALE, b1) : -1e30f;
            float s2 = (kc.x <= qp1) ? fmaf(accs[nf][2], SCALE, b0) : -1e30f;
            float s3 = (kc.y <= qp1) ? fmaf(accs[nf][3], SCALE, b1) : -1e30f;
            accs[nf][0] = s0; accs[nf][1] = s1; accs[nf][2] = s2; accs[nf][3] = s3;
            mx0 = fmaxf(mx0, fmaxf(s0, s1));
            mx1 = fmaxf(mx1, fmaxf(s2, s3));
        }
        mx0 = fmaxf(mx0, __shfl_xor_sync(0xFFFFFFFFu, mx0, 1));
        mx0 = fmaxf(mx0, __shfl_xor_sync(0xFFFFFFFFu, mx0, 2));
        mx1 = fmaxf(mx1, __shfl_xor_sync(0xFFFFFFFFu, mx1, 1));
        mx1 = fmaxf(mx1, __shfl_xor_sync(0xFFFFFFFFu, mx1, 2));

        float m0n = fmaxf(m0, mx0), m1n = fmaxf(m1, mx1);
        float c0 = __expf(m0 - m0n), c1 = __expf(m1 - m1n);
        m0 = m0n; m1 = m1n;

        float sum0 = 0.f, sum1 = 0.f;
#pragma unroll
        for (int nf = 0; nf < 8; nf++) {
            float p0 = __expf(accs[nf][0] - m0);
            float p1 = __expf(accs[nf][1] - m0);
            float p2 = __expf(accs[nf][2] - m1);
            float p3 = __expf(accs[nf][3] - m1);
            accs[nf][0] = p0; accs[nf][1] = p1; accs[nf][2] = p2; accs[nf][3] = p3;
            sum0 += p0 + p1; sum1 += p2 + p3;
        }
        l0 = l0 * c0 + sum0;
        l1 = l1 * c1 + sum1;
#pragma unroll
        for (int nf = 0; nf < 10; nf++) {
            o[nf][0] *= c0; o[nf][1] *= c0;
            o[nf][2] *= c1; o[nf][3] *= c1;
        }

        // ---- P fragments (hi/lo) ----
        uint32_t ph[4][4], pl[4][4];
#pragma unroll
        for (int ks2 = 0; ks2 < 4; ks2++) {
            split2(accs[2*ks2][0],   accs[2*ks2][1],   ph[ks2][0], pl[ks2][0]);
            split2(accs[2*ks2][2],   accs[2*ks2][3],   ph[ks2][1], pl[ks2][1]);
            split2(accs[2*ks2+1][0], accs[2*ks2+1][1], ph[ks2][2], pl[ks2][2]);
            split2(accs[2*ks2+1][2], accs[2*ks2+1][3], ph[ks2][3], pl[ks2][3]);
        }

        // ---- O += P V  (bf16x3, pass-reordered) ----
#pragma unroll
        for (int ks2 = 0; ks2 < 4; ks2++) {
            uint32_t bvh[5][4], bvl[5][4];
#pragma unroll
            for (int nfp = 0; nfp < 5; nfp++) {
                uint32_t row = (uint32_t)(ks2 * 16 + (mq & 1) * 8 + (lane & 7));
                uint32_t col = (uint32_t)((nfp * 2 + (mq >> 1)) * 8);
                uint32_t ad = st + 2 * (T_ELEMS * 2) + (row * ARS + col) * 2;
                ldsm_x4t(bvh[nfp], ad);
                ldsm_x4t(bvl[nfp], ad + T_ELEMS * 2);
            }
#pragma unroll
            for (int nfp = 0; nfp < 5; nfp++) {
                mma16816(o[nfp*2],   ph[ks2], &bvh[nfp][0]);
                mma16816(o[nfp*2+1], ph[ks2], &bvh[nfp][2]);
            }
#pragma unroll
            for (int nfp = 0; nfp < 5; nfp++) {
                mma16816(o[nfp*2],   ph[ks2], &bvl[nfp][0]);
                mma16816(o[nfp*2+1], ph[ks2], &bvl[nfp][2]);
            }
#pragma unroll
            for (int nfp = 0; nfp < 5; nfp++) {
                mma16816(o[nfp*2],   pl[ks2], &bvh[nfp][0]);
                mma16816(o[nfp*2+1], pl[ks2], &bvh[nfp][2]);
            }
        }
        __syncthreads();
    }

    // ---- epilogue ----
    l0 += __shfl_xor_sync(0xFFFFFFFFu, l0, 1);
    l0 += __shfl_xor_sync(0xFFFFFFFFu, l0, 2);
    l1 += __shfl_xor_sync(0xFFFFFFFFu, l1, 1);
    l1 += __shfl_xor_sync(0xFFFFFFFFu, l1, 2);
    float inv0 = 1.f / l0, inv1 = 1.f / l1;

    float* op0 = g_attn + (size_t)r0 * HID + h * HD;
#pragma unroll
    for (int nf = 0; nf < 10; nf++) {
        int col = nf * 8 + cp;
        *(float2*)(op0 + col)           = make_float2(o[nf][0] * inv0, o[nf][1] * inv0);
        *(float2*)(op0 + 8 * HID + col) = make_float2(o[nf][2] * inv1, o[nf][3] * inv1);
    }
}

// ---------------- launch -------------------------------------------------------
extern "C" void kernel_launch(void* const* d_in, const int* in_sizes, int n_in,
                              void* d_out, int out_size)
{
    const int*   pos  = nullptr;
    const float* hs   = nullptr;
    const float* wqkv = nullptr;
    const float* wout = nullptr;
    for (int i = 0; i < n_in; i++) {
        switch (in_sizes[i]) {
            case S:           pos  = (const int*)d_in[i];   break;
            case S * HID:     hs   = (const float*)d_in[i]; break;
            case HID * N_QKV: wqkv = (const float*)d_in[i]; break;
            case HID * HID:   wout = (const float*)d_in[i]; break;
        }
    }
    if (!pos || !hs || !wqkv || !wout) return;

    cudaFuncSetAttribute(mma_gemm, cudaFuncAttributeMaxDynamicSharedMemorySize, GEMM_SMEM);
    cudaFuncSetAttribute(attn_mma, cudaFuncAttributeMaxDynamicSharedMemorySize, ATTN_SMEM);

    __nv_bfloat16 *ahi, *alo, *wqh, *wql, *woh, *wol, *ath, *atl;
    float* attn_ptr;
    cudaGetSymbolAddress((void**)&ahi, g_a_hi);
    cudaGetSymbolAddress((void**)&alo, g_a_lo);
    cudaGetSymbolAddress((void**)&wqh, g_wqkv_hi);
    cudaGetSymbolAddress((void**)&wql, g_wqkv_lo);
    cudaGetSymbolAddress((void**)&woh, g_wout_hi);
    cudaGetSymbolAddress((void**)&wol, g_wout_lo);
    cudaGetSymbolAddress((void**)&ath, g_at_hi);
    cudaGetSymbolAddress((void**)&atl, g_at_lo);
    cudaGetSymbolAddress((void**)&attn_ptr, g_attn);

    // conversions
    conv_split<<<(S * HID) / 256, 256>>>(hs, ahi, alo, S * HID);
    convt_split<<<dim3(N_QKV / 32, HID / 32), dim3(32, 8)>>>(wqkv, wqh, wql, HID, N_QKV);
    convt_split<<<dim3(HID / 32, HID / 32), dim3(32, 8)>>>(wout, woh, wol, HID, HID);

    // 1) QKV projection (scatter epilogue into per-head q/k/v, fp32)
    mma_gemm<<<dim3(N_QKV / BNg, S / BMg), 256, GEMM_SMEM>>>(ahi, alo, wqh, wql, nullptr, HID, N_QKV, 1);

    // 2) RoPE (fp32 in-place)
    rope_kernel<<<(NH * S * 32) / 256, 256>>>(pos);

    // 3) q/k/v -> bf16 hi/lo (+ pos -> float)
    conv_qkv<<<(NH * S * HD) / 256, 256>>>(pos);

    // 4) flash attention (HMMA)
    attn_mma<<<dim3(S / AQB, NH), 256, ATTN_SMEM>>>();

    // 5) attn output -> bf16 split, then output projection
    conv_split<<<(S * HID) / 256, 256>>>(attn_ptr, ath, atl, S * HID);
    mma_gemm<<<dim3(HID / BNg, S / BMg), 256, GEMM_SMEM>>>(ath, atl, woh, wol, (float*)d_out, HID, HID, 0);
}

// round 6
// speedup vs baseline: 3.1273x; 1.0708x over previous
#include <cuda_runtime.h>
#include <cuda_bf16.h>
#include <cstdint>

// Problem constants
#define S    2048
#define HID  2560
#define NH   32
#define HD   80
#define N_QKV (3*HID)          // 7680
#define SCALE 0.11180339887498949f   // 80^-0.5

// ---------------- scratch (device globals; no allocs allowed) ---------------
__device__ float g_q[NH * S * HD];
__device__ float g_k[NH * S * HD];
__device__ float g_v[NH * S * HD];
__device__ float g_attn[S * HID];
__device__ float g_posf[S];

__device__ __nv_bfloat16 g_a_hi[S * HID],      g_a_lo[S * HID];        // hidden (M,K)
__device__ __nv_bfloat16 g_wqkv_hi[N_QKV*HID], g_wqkv_lo[N_QKV*HID];   // (N,K) transposed
__device__ __nv_bfloat16 g_wout_hi[HID*HID],   g_wout_lo[HID*HID];     // (N,K) transposed
__device__ __nv_bfloat16 g_at_hi[S * HID],     g_at_lo[S * HID];       // attn out (M,K)

__device__ __nv_bfloat16 g_qh[NH*S*HD], g_ql[NH*S*HD];
__device__ __nv_bfloat16 g_kh[NH*S*HD], g_kl[NH*S*HD];
__device__ __nv_bfloat16 g_vh[NH*S*HD], g_vl[NH*S*HD];

// ---------------- PTX helpers ------------------------------------------------
__device__ __forceinline__ uint32_t smem_u32(const void* p) {
    return (uint32_t)__cvta_generic_to_shared((void*)p);
}
__device__ __forceinline__ void cp16(uint32_t s, const void* g) {
    asm volatile("cp.async.cg.shared.global [%0], [%1], 16;" :: "r"(s), "l"(g) : "memory");
}
__device__ __forceinline__ void ldsm_x4(uint32_t* r, uint32_t addr) {
    asm volatile("ldmatrix.sync.aligned.m8n8.x4.shared.b16 {%0,%1,%2,%3}, [%4];"
                 : "=r"(r[0]), "=r"(r[1]), "=r"(r[2]), "=r"(r[3]) : "r"(addr));
}
__device__ __forceinline__ void ldsm_x4t(uint32_t* r, uint32_t addr) {
    asm volatile("ldmatrix.sync.aligned.m8n8.x4.trans.shared.b16 {%0,%1,%2,%3}, [%4];"
                 : "=r"(r[0]), "=r"(r[1]), "=r"(r[2]), "=r"(r[3]) : "r"(addr));
}
__device__ __forceinline__ void ldsm_x2(uint32_t* r, uint32_t addr) {
    asm volatile("ldmatrix.sync.aligned.m8n8.x2.shared.b16 {%0,%1}, [%2];"
                 : "=r"(r[0]), "=r"(r[1]) : "r"(addr));
}
__device__ __forceinline__ void mma16816(float* d, const uint32_t* a, const uint32_t* b) {
    asm volatile("mma.sync.aligned.m16n8k16.row.col.f32.bf16.bf16.f32 "
                 "{%0,%1,%2,%3}, {%4,%5,%6,%7}, {%8,%9}, {%0,%1,%2,%3};"
                 : "+f"(d[0]), "+f"(d[1]), "+f"(d[2]), "+f"(d[3])
                 : "r"(a[0]), "r"(a[1]), "r"(a[2]), "r"(a[3]), "r"(b[0]), "r"(b[1]));
}
__device__ __forceinline__ void split2(float a, float b, uint32_t& hi, uint32_t& lo) {
    __nv_bfloat162 h, l;
    h.x = __float2bfloat16(a);
    h.y = __float2bfloat16(b);
    l.x = __float2bfloat16(a - __bfloat162float(h.x));
    l.y = __float2bfloat16(b - __bfloat162float(h.y));
    hi = *(uint32_t*)&h;
    lo = *(uint32_t*)&l;
}

// ---------------- HMMA GEMM: D[M,N] = A[M,K] @ B[N,K]^T (bf16x3 split) ------
#define BMg 128
#define BNg 128
#define RSg 40                      // bf16 row stride (32 data + 8 pad)
#define TENg (128*RSg)              // bf16 elems per tensor tile (5120)
#define STAGEg (4*TENg)             // per stage (A_hi, A_lo, B_hi, B_lo)
#define GEMM_SMEM (2*STAGEg*2)      // bytes (81920)

__global__ __launch_bounds__(256, 2)
void mma_gemm(const __nv_bfloat16* __restrict__ Ahi, const __nv_bfloat16* __restrict__ Alo,
              const __nv_bfloat16* __restrict__ Bhi, const __nv_bfloat16* __restrict__ Blo,
              float* __restrict__ C, int K, int N, int mode)
{
    extern __shared__ __align__(128) __nv_bfloat16 sm[];
    const int tid  = threadIdx.x;
    const int wid  = tid >> 5;
    const int lane = tid & 31;
    const int wr   = wid >> 2;
    const int wc   = wid & 3;
    const int rowBase = blockIdx.y * BMg;
    const int colBase = blockIdx.x * BNg;
    const uint32_t smbase = smem_u32(sm);

    float acc[4][4][4];
#pragma unroll
    for (int i = 0; i < 4; i++)
#pragma unroll
        for (int j = 0; j < 4; j++)
#pragma unroll
            for (int k = 0; k < 4; k++) acc[i][j][k] = 0.f;

    const int NC = K >> 5;

    {
#pragma unroll
        for (int t = 0; t < 2; t++) {
            int idx = tid + t * 256;
            int row = idx >> 2, seg = idx & 3;
            uint32_t so = smbase + (uint32_t)(row * RSg + seg * 8) * 2;
            size_t gA = (size_t)(rowBase + row) * K + seg * 8;
            size_t gB = (size_t)(colBase + row) * K + seg * 8;
            cp16(so,                Ahi + gA);
            cp16(so + TENg * 2,     Alo + gA);
            cp16(so + 2 * TENg * 2, Bhi + gB);
            cp16(so + 3 * TENg * 2, Blo + gB);
        }
        asm volatile("cp.async.commit_group;" ::: "memory");
    }

    for (int c = 0; c < NC; c++) {
        const int s = c & 1;
        if (c + 1 < NC) {
            const int kt = (c + 1) << 5;
            const uint32_t sb = smbase + ((c + 1) & 1) * STAGEg * 2;
#pragma unroll
            for (int t = 0; t < 2; t++) {
                int idx = tid + t * 256;
                int row = idx >> 2, seg = idx & 3;
                uint32_t so = sb + (uint32_t)(row * RSg + seg * 8) * 2;
                size_t gA = (size_t)(rowBase + row) * K + kt + seg * 8;
                size_t gB = (size_t)(colBase + row) * K + kt + seg * 8;
                cp16(so,                Ahi + gA);
                cp16(so + TENg * 2,     Alo + gA);
                cp16(so + 2 * TENg * 2, Bhi + gB);
                cp16(so + 3 * TENg * 2, Blo + gB);
            }
        }
        asm volatile("cp.async.commit_group;" ::: "memory");
        asm volatile("cp.async.wait_group 1;" ::: "memory");
        __syncthreads();

        const uint32_t sb = smbase + s * STAGEg * 2;
#pragma unroll
        for (int ks = 0; ks < 2; ks++) {
            const int kof = ks * 16;
            uint32_t ah[4][4], al[4][4];
#pragma unroll
            for (int mf = 0; mf < 4; mf++) {
                int row = wr * 64 + mf * 16 + (lane & 15);
                int col = kof + (lane >> 4) * 8;
                uint32_t ad = sb + (uint32_t)(row * RSg + col) * 2;
                ldsm_x4(ah[mf], ad);
                ldsm_x4(al[mf], ad + TENg * 2);
            }
            uint32_t bh[4][2], bl[4][2];
#pragma unroll
            for (int nf = 0; nf < 4; nf++) {
                int brow = wc * 32 + nf * 8 + (lane & 7);
                int bcol = kof + ((lane >> 3) & 1) * 8;
                uint32_t bd = sb + 2 * TENg * 2 + (uint32_t)(brow * RSg + bcol) * 2;
                ldsm_x2(bh[nf], bd);
                ldsm_x2(bl[nf], bd + TENg * 2);
            }
#pragma unroll
            for (int mf = 0; mf < 4; mf++)
#pragma unroll
                for (int nf = 0; nf < 4; nf++)
                    mma16816(acc[mf][nf], ah[mf], bh[nf]);
#pragma unroll
            for (int mf = 0; mf < 4; mf++)
#pragma unroll
                for (int nf = 0; nf < 4; nf++)
                    mma16816(acc[mf][nf], ah[mf], bl[nf]);
#pragma unroll
            for (int mf = 0; mf < 4; mf++)
#pragma unroll
                for (int nf = 0; nf < 4; nf++)
                    mma16816(acc[mf][nf], al[mf], bh[nf]);
        }
        __syncthreads();
    }

#pragma unroll
    for (int mf = 0; mf < 4; mf++) {
#pragma unroll
        for (int nf = 0; nf < 4; nf++) {
            int row = rowBase + wr * 64 + mf * 16 + (lane >> 2);
            int col = colBase + wc * 32 + nf * 8 + (lane & 3) * 2;
            if (mode == 0) {
                *(float2*)(C + (size_t)row * N + col) =
                    make_float2(acc[mf][nf][0], acc[mf][nf][1]);
                *(float2*)(C + (size_t)(row + 8) * N + col) =
                    make_float2(acc[mf][nf][2], acc[mf][nf][3]);
            } else {
                int p   = col / HID;
                int rem = col - p * HID;
                int h   = rem / HD;
                int d   = rem - h * HD;
                float* dst = (p == 0) ? g_q : ((p == 1) ? g_k : g_v);
                *(float2*)(&dst[((size_t)h * S + row) * HD + d]) =
                    make_float2(acc[mf][nf][0], acc[mf][nf][1]);
                *(float2*)(&dst[((size_t)h * S + row + 8) * HD + d]) =
                    make_float2(acc[mf][nf][2], acc[mf][nf][3]);
            }
        }
    }
}

// ---------------- conversions ------------------------------------------------
__global__ void conv_split(const float* __restrict__ x, __nv_bfloat16* __restrict__ hi,
                           __nv_bfloat16* __restrict__ lo, int n)
{
    int i = blockIdx.x * blockDim.x + threadIdx.x;
    if (i >= n) return;
    float v = x[i];
    __nv_bfloat16 h = __float2bfloat16(v);
    hi[i] = h;
    lo[i] = __float2bfloat16(v - __bfloat162float(h));
}

__global__ void convt_split(const float* __restrict__ W, __nv_bfloat16* __restrict__ hi,
                            __nv_bfloat16* __restrict__ lo, int K, int N)
{
    __shared__ float t[32][33];
    int n0 = blockIdx.x * 32, k0 = blockIdx.y * 32;
    for (int r = threadIdx.y; r < 32; r += 8)
        t[r][threadIdx.x] = W[(size_t)(k0 + r) * N + n0 + threadIdx.x];
    __syncthreads();
    for (int r = threadIdx.y; r < 32; r += 8) {
        float v = t[threadIdx.x][r];
        __nv_bfloat16 h = __float2bfloat16(v);
        size_t o = (size_t)(n0 + r) * K + k0 + threadIdx.x;
        hi[o] = h;
        lo[o] = __float2bfloat16(v - __bfloat162float(h));
    }
}

// split q/k/v (post-rope) into bf16 hi/lo; also pos -> float
__global__ void conv_qkv(const int* __restrict__ pos)
{
    int i = blockIdx.x * blockDim.x + threadIdx.x;
    if (i < S) g_posf[i] = (float)pos[i];
    if (i >= NH * S * HD) return;
    float q = g_q[i];
    __nv_bfloat16 qh = __float2bfloat16(q);
    g_qh[i] = qh; g_ql[i] = __float2bfloat16(q - __bfloat162float(qh));
    float k = g_k[i];
    __nv_bfloat16 kh = __float2bfloat16(k);
    g_kh[i] = kh; g_kl[i] = __float2bfloat16(k - __bfloat162float(kh));
    float v = g_v[i];
    __nv_bfloat16 vh = __float2bfloat16(v);
    g_vh[i] = vh; g_vl[i] = __float2bfloat16(v - __bfloat162float(vh));
}

// ---------------- RoPE --------------------------------------------------------
__global__ void rope_kernel(const int* __restrict__ pos_ids)
{
    int idx = blockIdx.x * blockDim.x + threadIdx.x;
    int d = idx & 31;
    int s = (idx >> 5) & (S - 1);
    int h = idx >> 16;
    if (h >= NH) return;

    float posf = (float)pos_ids[s];
    float inv  = exp2f(-0.415241011861f * (float)d);
    float ang  = posf * inv;
    float c, sn;
    sincosf(ang, &sn, &c);

    size_t base = ((size_t)h * S + s) * HD;
    float q1 = g_q[base + d], q2 = g_q[base + d + 32];
    g_q[base + d]      = q1 * c - q2 * sn;
    g_q[base + d + 32] = q2 * c + q1 * sn;
    float k1 = g_k[base + d], k2 = g_k[base + d + 32];
    g_k[base + d]      = k1 * c - k2 * sn;
    g_k[base + d + 32] = k2 * c + k1 * sn;
}

// ---------------- HMMA flash attention with ALiBi ----------------------------
#define AQB 128
#define AKB 64
#define ARS 88                          // padded row stride (bf16)
#define T_ELEMS (AKB*ARS)               // 5632
#define KPOS_OFF (4*T_ELEMS*2)          // 45056
#define ASTAGE (KPOS_OFF + 256)         // 45312 (128-aligned)
#define ATTN_SMEM (2*ASTAGE)            // 90624

__global__ __launch_bounds__(256)
void attn_mma()
{
    extern __shared__ char smbuf[];
    const int h     = blockIdx.y;
    const int qtile = gridDim.x - 1 - blockIdx.x;
    const int q0    = qtile * AQB;
    const int tid   = threadIdx.x;
    const int wid   = tid >> 5;
    const int lane  = tid & 31;
    const uint32_t sb = smem_u32(smbuf);

    // Q fragments (registers, whole kernel)
    const int r0 = q0 + wid * 16 + (lane >> 2);     // global q row (and +8)
    const int cp = (lane & 3) * 2;
    uint32_t qfh[5][4], qfl[5][4];
    {
        const __nv_bfloat16* qhp = g_qh + ((size_t)h * S + r0) * HD;
        const __nv_bfloat16* qlp = g_ql + ((size_t)h * S + r0) * HD;
#pragma unroll
        for (int ks = 0; ks < 5; ks++) {
            int c = ks * 16 + cp;
            qfh[ks][0] = *(const uint32_t*)(qhp + c);
            qfh[ks][1] = *(const uint32_t*)(qhp + 8 * HD + c);
            qfh[ks][2] = *(const uint32_t*)(qhp + c + 8);
            qfh[ks][3] = *(const uint32_t*)(qhp + 8 * HD + c + 8);
            qfl[ks][0] = *(const uint32_t*)(qlp + c);
            qfl[ks][1] = *(const uint32_t*)(qlp + 8 * HD + c);
            qfl[ks][2] = *(const uint32_t*)(qlp + c + 8);
            qfl[ks][3] = *(const uint32_t*)(qlp + 8 * HD + c + 8);
        }
    }
    const float qp0 = g_posf[r0];
    const float qp1 = g_posf[r0 + 8];
    const float slope = exp2f(-0.25f * (float)(h + 1));

    float o[10][4];
#pragma unroll
    for (int i = 0; i < 10; i++)
#pragma unroll
        for (int j = 0; j < 4; j++) o[i][j] = 0.f;
    float m0 = -1e30f, m1 = -1e30f, l0 = 0.f, l1 = 0.f;

    const int NT = (q0 + AQB) / AKB;

    auto issue = [&](int t) {
        const uint32_t dst = sb + (t & 1) * ASTAGE;
        const int kt = t * AKB;
#pragma unroll
        for (int it = 0; it < 10; it++) {
            int idx = it * 256 + tid;            // 0..2559
            int tensor = idx / 640;
            int rem = idx - tensor * 640;
            int row = rem / 10, seg = rem - row * 10;
            const __nv_bfloat16* base =
                (tensor == 0) ? g_kh : (tensor == 1) ? g_kl : (tensor == 2) ? g_vh : g_vl;
            const __nv_bfloat16* src = base + ((size_t)h * S + kt + row) * HD + seg * 8;
            cp16(dst + (uint32_t)tensor * (T_ELEMS * 2) + (uint32_t)(row * ARS + seg * 8) * 2, src);
        }
        if (tid < 16) cp16(dst + KPOS_OFF + tid * 16, g_posf + kt + tid * 4);
    };

    issue(0);
    asm volatile("cp.async.commit_group;" ::: "memory");

    for (int t = 0; t < NT; t++) {
        if (t + 1 < NT) issue(t + 1);
        asm volatile("cp.async.commit_group;" ::: "memory");
        asm volatile("cp.async.wait_group 1;" ::: "memory");
        __syncthreads();

        const uint32_t st = sb + (t & 1) * ASTAGE;
        const float* kposb = (const float*)(smbuf + (t & 1) * ASTAGE + KPOS_OFF);

        // ---- S = Q K^T  (bf16x3, pass-reordered) ----
        float accs[8][4];
#pragma unroll
        for (int nf = 0; nf < 8; nf++)
#pragma unroll
            for (int e = 0; e < 4; e++) accs[nf][e] = 0.f;

        const int mq = lane >> 3;                 // 0..3 matrix index for ldsm_x4
#pragma unroll
        for (int ks = 0; ks < 5; ks++) {
            uint32_t bh[4][4], bl[4][4];
#pragma unroll
            for (int nfp = 0; nfp < 4; nfp++) {
                uint32_t row = (uint32_t)((nfp * 2 + (mq >> 1)) * 8 + (lane & 7));
                uint32_t col = (uint32_t)(ks * 16 + (mq & 1) * 8);
                uint32_t ad = st + (row * ARS + col) * 2;
                ldsm_x4(bh[nfp], ad);
                ldsm_x4(bl[nfp], ad + T_ELEMS * 2);
            }
#pragma unroll
            for (int nfp = 0; nfp < 4; nfp++) {
                mma16816(accs[nfp*2],   qfh[ks], &bh[nfp][0]);
                mma16816(accs[nfp*2+1], qfh[ks], &bh[nfp][2]);
            }
#pragma unroll
            for (int nfp = 0; nfp < 4; nfp++) {
                mma16816(accs[nfp*2],   qfh[ks], &bl[nfp][0]);
                mma16816(accs[nfp*2+1], qfh[ks], &bl[nfp][2]);
            }
#pragma unroll
            for (int nfp = 0; nfp < 4; nfp++) {
                mma16816(accs[nfp*2],   qfl[ks], &bh[nfp][0]);
                mma16816(accs[nfp*2+1], qfl[ks], &bh[nfp][2]);
            }
        }

        // ---- masked/biased softmax (online) ----
        float mx0 = -1e30f, mx1 = -1e30f;
#pragma unroll
        for (int nf = 0; nf < 8; nf++) {
            float2 kc = *(const float2*)(kposb + nf * 8 + cp);
            float b0 = slope * kc.x, b1 = slope * kc.y;
            float s0 = (kc.x <= qp0) ? fmaf(accs[nf][0], SCALE, b0) : -1e30f;
            float s1 = (kc.y <= qp0) ? fmaf(accs[nf][1], SCALE, b1) : -1e30f;
            float s2 = (kc.x <= qp1) ? fmaf(accs[nf][2], SCALE, b0) : -1e30f;
            float s3 = (kc.y <= qp1) ? fmaf(accs[nf][3], SCALE, b1) : -1e30f;
            accs[nf][0] = s0; accs[nf][1] = s1; accs[nf][2] = s2; accs[nf][3] = s3;
            mx0 = fmaxf(mx0, fmaxf(s0, s1));
            mx1 = fmaxf(mx1, fmaxf(s2, s3));
        }
        mx0 = fmaxf(mx0, __shfl_xor_sync(0xFFFFFFFFu, mx0, 1));
        mx0 = fmaxf(mx0, __shfl_xor_sync(0xFFFFFFFFu, mx0, 2));
        mx1 = fmaxf(mx1, __shfl_xor_sync(0xFFFFFFFFu, mx1, 1));
        mx1 = fmaxf(mx1, __shfl_xor_sync(0xFFFFFFFFu, mx1, 2));

        float m0n = fmaxf(m0, mx0), m1n = fmaxf(m1, mx1);
        float c0 = __expf(m0 - m0n), c1 = __expf(m1 - m1n);
        m0 = m0n; m1 = m1n;

        float sum0 = 0.f, sum1 = 0.f;
#pragma unroll
        for (int nf = 0; nf < 8; nf++) {
            float p0 = __expf(accs[nf][0] - m0);
            float p1 = __expf(accs[nf][1] - m0);
            float p2 = __expf(accs[nf][2] - m1);
            float p3 = __expf(accs[nf][3] - m1);
            accs[nf][0] = p0; accs[nf][1] = p1; accs[nf][2] = p2; accs[nf][3] = p3;
            sum0 += p0 + p1; sum1 += p2 + p3;
        }
        l0 = l0 * c0 + sum0;
        l1 = l1 * c1 + sum1;
#pragma unroll
        for (int nf = 0; nf < 10; nf++) {
            o[nf][0] *= c0; o[nf][1] *= c0;
            o[nf][2] *= c1; o[nf][3] *= c1;
        }

        // ---- P fragments (hi/lo) ----
        uint32_t ph[4][4], pl[4][4];
#pragma unroll
        for (int ks2 = 0; ks2 < 4; ks2++) {
            split2(accs[2*ks2][0],   accs[2*ks2][1],   ph[ks2][0], pl[ks2][0]);
            split2(accs[2*ks2][2],   accs[2*ks2][3],   ph[ks2][1], pl[ks2][1]);
            split2(accs[2*ks2+1][0], accs[2*ks2+1][1], ph[ks2][2], pl[ks2][2]);
            split2(accs[2*ks2+1][2], accs[2*ks2+1][3], ph[ks2][3], pl[ks2][3]);
        }

        // ---- O += P V  (bf16x3, pass-reordered) ----
#pragma unroll
        for (int ks2 = 0; ks2 < 4; ks2++) {
            uint32_t bvh[5][4], bvl[5][4];
#pragma unroll
            for (int nfp = 0; nfp < 5; nfp++) {
                uint32_t row = (uint32_t)(ks2 * 16 + (mq & 1) * 8 + (lane & 7));
                uint32_t col = (uint32_t)((nfp * 2 + (mq >> 1)) * 8);
                uint32_t ad = st + 2 * (T_ELEMS * 2) + (row * ARS + col) * 2;
                ldsm_x4t(bvh[nfp], ad);
                ldsm_x4t(bvl[nfp], ad + T_ELEMS * 2);
            }
#pragma unroll
            for (int nfp = 0; nfp < 5; nfp++) {
                mma16816(o[nfp*2],   ph[ks2], &bvh[nfp][0]);
                mma16816(o[nfp*2+1], ph[ks2], &bvh[nfp][2]);
            }
#pragma unroll
            for (int nfp = 0; nfp < 5; nfp++) {
                mma16816(o[nfp*2],   ph[ks2], &bvl[nfp][0]);
                mma16816(o[nfp*2+1], ph[ks2], &bvl[nfp][2]);
            }
#pragma unroll
            for (int nfp = 0; nfp < 5; nfp++) {
                mma16816(o[nfp*2],   pl[ks2], &bvh[nfp][0]);
                mma16816(o[nfp*2+1], pl[ks2], &bvh[nfp][2]);
            }
        }
        __syncthreads();
    }

    // ---- epilogue ----
    l0 += __shfl_xor_sync(0xFFFFFFFFu, l0, 1);
    l0 += __shfl_xor_sync(0xFFFFFFFFu, l0, 2);
    l1 += __shfl_xor_sync(0xFFFFFFFFu, l1, 1);
    l1 += __shfl_xor_sync(0xFFFFFFFFu, l1, 2);
    float inv0 = 1.f / l0, inv1 = 1.f / l1;

    float* op0 = g_attn + (size_t)r0 * HID + h * HD;
#pragma unroll
    for (int nf = 0; nf < 10; nf++) {
        int col = nf * 8 + cp;
        *(float2*)(op0 + col)           = make_float2(o[nf][0] * inv0, o[nf][1] * inv0);
        *(float2*)(op0 + 8 * HID + col) = make_float2(o[nf][2] * inv1, o[nf][3] * inv1);
    }
}

// ---------------- launch -------------------------------------------------------
extern "C" void kernel_launch(void* const* d_in, const int* in_sizes, int n_in,
                              void* d_out, int out_size)
{
    const int*   pos  = nullptr;
    const float* hs   = nullptr;
    const float* wqkv = nullptr;
    const float* wout = nullptr;
    for (int i = 0; i < n_in; i++) {
        switch (in_sizes[i]) {
            case S:           pos  = (const int*)d_in[i];   break;
            case S * HID:     hs   = (const float*)d_in[i]; break;
            case HID * N_QKV: wqkv = (const float*)d_in[i]; break;
            case HID * HID:   wout = (const float*)d_in[i]; break;
        }
    }
    if (!pos || !hs || !wqkv || !wout) return;

    cudaFuncSetAttribute(mma_gemm, cudaFuncAttributeMaxDynamicSharedMemorySize, GEMM_SMEM);
    cudaFuncSetAttribute(attn_mma, cudaFuncAttributeMaxDynamicSharedMemorySize, ATTN_SMEM);

    __nv_bfloat16 *ahi, *alo, *wqh, *wql, *woh, *wol, *ath, *atl;
    float* attn_ptr;
    cudaGetSymbolAddress((void**)&ahi, g_a_hi);
    cudaGetSymbolAddress((void**)&alo, g_a_lo);
    cudaGetSymbolAddress((void**)&wqh, g_wqkv_hi);
    cudaGetSymbolAddress((void**)&wql, g_wqkv_lo);
    cudaGetSymbolAddress((void**)&woh, g_wout_hi);
    cudaGetSymbolAddress((void**)&wol, g_wout_lo);
    cudaGetSymbolAddress((void**)&ath, g_at_hi);
    cudaGetSymbolAddress((void**)&atl, g_at_lo);
    cudaGetSymbolAddress((void**)&attn_ptr, g_attn);

    // conversions
    conv_split<<<(S * HID) / 256, 256>>>(hs, ahi, alo, S * HID);
    convt_split<<<dim3(N_QKV / 32, HID / 32), dim3(32, 8)>>>(wqkv, wqh, wql, HID, N_QKV);
    convt_split<<<dim3(HID / 32, HID / 32), dim3(32, 8)>>>(wout, woh, wol, HID, HID);

    // 1) QKV projection (scatter epilogue into per-head q/k/v, fp32)
    mma_gemm<<<dim3(N_QKV / BNg, S / BMg), 256, GEMM_SMEM>>>(ahi, alo, wqh, wql, nullptr, HID, N_QKV, 1);

    // 2) RoPE (fp32 in-place)
    rope_kernel<<<(NH * S * 32) / 256, 256>>>(pos);

    // 3) q/k/v -> bf16 hi/lo (+ pos -> float)
    conv_qkv<<<(NH * S * HD) / 256, 256>>>(pos);

    // 4) flash attention (HMMA)
    attn_mma<<<dim3(S / AQB, NH), 256, ATTN_SMEM>>>();

    // 5) attn output -> bf16 split, then output projection
    conv_split<<<(S * HID) / 256, 256>>>(attn_ptr, ath, atl, S * HID);
    mma_gemm<<<dim3(HID / BNg, S / BMg), 256, GEMM_SMEM>>>(ath, atl, woh, wol, (float*)d_out, HID, HID, 0);
}